// round 2
// baseline (speedup 1.0000x reference)
#include <cuda_runtime.h>
#include <cuda_bf16.h>
#include <cstdint>

// ---------------- problem constants ----------------
#define BATCH   16384
#define KMER    17
#define EMB     16
#define HH      136          // hidden
#define LL      272          // input feature dim (= 2*HH)
#define GATES   544          // 4*HH
#define GCOLS   1088         // 2 dirs * 4H
#define GROWS   32768        // 2*BATCH (row = b*2 + t)
#define NL      3
#define OUTC    16
#define NCAPS   10

// ---------------- device scratch (statically allocated; no runtime alloc) ----
__device__ float g_X0[(size_t)BATCH * 2 * LL];   // (B,2,272) activations ping
__device__ float g_X1[(size_t)BATCH * 2 * LL];   // pong
__device__ float g_G [(size_t)GROWS * GCOLS];    // gate buffer (2B, 1088)
__device__ float g_Cf[(size_t)BATCH * HH];       // forward cell state after t0
__device__ float g_Cb[(size_t)BATCH * HH];       // backward cell state after t1

// ---------------- prep: build layer-0 input -------------------------------
// X[b,0,:] = embed[seq[b]].flatten() (17*16=272), X[b,1,:] = sig[b,:]
__global__ void prep_kernel(const int* __restrict__ seq,
                            const float* __restrict__ sig,
                            const float* __restrict__ embed,
                            float* __restrict__ X)
{
    int idx = blockIdx.x * blockDim.x + threadIdx.x;
    if (idx >= BATCH * LL) return;
    int b = idx / LL, r = idx % LL;
    int p = r >> 4, e = r & 15;
    int tok = seq[b * KMER + p];
    X[(size_t)b * 544 + r]       = embed[tok * EMB + e];
    X[(size_t)b * 544 + 272 + r] = sig[(size_t)b * LL + r];
}

// ---------------- SGEMM (NT): C[m,n] (+)= sum_k A[m,k]*B[n,k] (+ bias) ------
// A: (M,K) row-major lda ; B: (N,K) row-major ldb ; C: row-major ldc
// 128x128 block tile, 8x8 per thread, BK=8, 256 threads.
__global__ __launch_bounds__(256)
void sgemm_nt(const float* __restrict__ A, int lda,
              const float* __restrict__ Bm, int ldb,
              float* __restrict__ C, int ldc,
              int M, int N, int K,
              const float* __restrict__ bias1,
              const float* __restrict__ bias2,
              int accumulate)
{
    __shared__ float As[8][128];
    __shared__ float Bs[8][128];

    const int bm0 = blockIdx.y * 128;
    const int bn0 = blockIdx.x * 128;
    const int tid = threadIdx.x;
    const int tx  = tid & 15;          // 0..15 -> 8 cols each
    const int ty  = tid >> 4;          // 0..15 -> 8 rows each

    const int lrow = tid >> 1;         // 0..127
    const int lk   = (tid & 1) * 4;    // 0 or 4

    float acc[8][8];
    #pragma unroll
    for (int i = 0; i < 8; ++i)
        #pragma unroll
        for (int j = 0; j < 8; ++j) acc[i][j] = 0.f;

    for (int k0 = 0; k0 < K; k0 += 8) {
        // load A tile (always in-range rows here, but guard cheaply)
        {
            int gr = bm0 + lrow;
            float4 av = make_float4(0.f, 0.f, 0.f, 0.f);
            if (gr < M)
                av = *reinterpret_cast<const float4*>(A + (size_t)gr * lda + k0 + lk);
            As[lk + 0][lrow] = av.x; As[lk + 1][lrow] = av.y;
            As[lk + 2][lrow] = av.z; As[lk + 3][lrow] = av.w;
        }
        // load B tile (N may not be tile-multiple)
        {
            int gc = bn0 + lrow;
            float4 bv = make_float4(0.f, 0.f, 0.f, 0.f);
            if (gc < N)
                bv = *reinterpret_cast<const float4*>(Bm + (size_t)gc * ldb + k0 + lk);
            Bs[lk + 0][lrow] = bv.x; Bs[lk + 1][lrow] = bv.y;
            Bs[lk + 2][lrow] = bv.z; Bs[lk + 3][lrow] = bv.w;
        }
        __syncthreads();

        #pragma unroll
        for (int kk = 0; kk < 8; ++kk) {
            float4 a0 = *reinterpret_cast<const float4*>(&As[kk][ty * 8 + 0]);
            float4 a1 = *reinterpret_cast<const float4*>(&As[kk][ty * 8 + 4]);
            float4 b0 = *reinterpret_cast<const float4*>(&Bs[kk][tx * 8 + 0]);
            float4 b1 = *reinterpret_cast<const float4*>(&Bs[kk][tx * 8 + 4]);
            float ar[8] = {a0.x, a0.y, a0.z, a0.w, a1.x, a1.y, a1.z, a1.w};
            float br[8] = {b0.x, b0.y, b0.z, b0.w, b1.x, b1.y, b1.z, b1.w};
            #pragma unroll
            for (int i = 0; i < 8; ++i)
                #pragma unroll
                for (int j = 0; j < 8; ++j)
                    acc[i][j] = fmaf(ar[i], br[j], acc[i][j]);
        }
        __syncthreads();
    }

    #pragma unroll
    for (int i = 0; i < 8; ++i) {
        int r = bm0 + ty * 8 + i;
        if (r >= M) continue;
        #pragma unroll
        for (int j = 0; j < 8; ++j) {
            int c = bn0 + tx * 8 + j;
            if (c >= N) continue;
            float v = acc[i][j];
            if (bias1) v += bias1[c] + bias2[c];
            float* p = C + (size_t)r * ldc + c;
            if (accumulate) *p += v; else *p = v;
        }
    }
}

// ---------------- LSTM cells (elementwise) ---------------------------------
__device__ __forceinline__ float sigm(float x) { return 1.f / (1.f + expf(-x)); }

// step 1: h=c=0.  forward t=0 (dir0), backward t=1 (dir1).
__global__ void cell1_kernel(const float* __restrict__ G,
                             float* __restrict__ Xn,
                             float* __restrict__ Cf,
                             float* __restrict__ Cb)
{
    int idx = blockIdx.x * blockDim.x + threadIdx.x;
    if (idx >= BATCH * HH) return;
    int b = idx / HH, j = idx % HH;

    const float* g = G + (size_t)(2 * b) * GCOLS;            // t=0, dir0 @ col 0
    float c  = sigm(g[j]) * tanhf(g[272 + j]);
    float h  = sigm(g[408 + j]) * tanhf(c);
    Cf[idx] = c;
    Xn[(size_t)b * 544 + j] = h;                              // hf0 -> x[b,0,0:136]

    const float* g2 = G + (size_t)(2 * b + 1) * GCOLS + 544;  // t=1, dir1
    float c2 = sigm(g2[j]) * tanhf(g2[272 + j]);
    float h2 = sigm(g2[408 + j]) * tanhf(c2);
    Cb[idx] = c2;
    Xn[(size_t)b * 544 + 408 + j] = h2;                       // hb1 -> x[b,1,136:272]
}

// step 2: uses carried cell state. forward t=1 (dir0), backward t=0 (dir1).
__global__ void cell2_kernel(const float* __restrict__ G,
                             float* __restrict__ Xn,
                             const float* __restrict__ Cf,
                             const float* __restrict__ Cb)
{
    int idx = blockIdx.x * blockDim.x + threadIdx.x;
    if (idx >= BATCH * HH) return;
    int b = idx / HH, j = idx % HH;

    const float* g = G + (size_t)(2 * b + 1) * GCOLS;         // t=1, dir0
    float c  = sigm(g[136 + j]) * Cf[idx] + sigm(g[j]) * tanhf(g[272 + j]);
    float h  = sigm(g[408 + j]) * tanhf(c);
    Xn[(size_t)b * 544 + 272 + j] = h;                        // hf1 -> x[b,1,0:136]

    const float* g2 = G + (size_t)(2 * b) * GCOLS + 544;      // t=0, dir1
    float c2 = sigm(g2[136 + j]) * Cb[idx] + sigm(g2[j]) * tanhf(g2[272 + j]);
    float h2 = sigm(g2[408 + j]) * tanhf(c2);
    Xn[(size_t)b * 544 + 136 + j] = h2;                       // hb0 -> x[b,0,136:272]
}

// ---------------- fused head: conv -> squash -> u_hat -> v -> fc -> softmax -
// Routing collapses: softmax over singleton axis => c == 1, so v = squash(sum_c u_hat).
#define EPB 2   // batch elements per block (128 threads each)
__global__ __launch_bounds__(128 * EPB)
void head_kernel(const float* __restrict__ X,
                 const float* __restrict__ conv_w,
                 const float* __restrict__ conv_b,
                 const float* __restrict__ W_caps,
                 const float* __restrict__ fc1_w,
                 const float* __restrict__ fc1_b,
                 const float* __restrict__ fc2_w,
                 const float* __restrict__ fc2_b,
                 float* __restrict__ out, int out_size)
{
    __shared__ float u[EPB][NCAPS][LL];
    __shared__ float scale[EPB][NCAPS];
    __shared__ float uhat[EPB][NCAPS][OUTC];
    __shared__ float vv[EPB][OUTC];
    __shared__ float wred[EPB][4][2];

    const int e = threadIdx.x >> 7;      // element within block
    const int t = threadIdx.x & 127;     // 0..127
    const int b = blockIdx.x * EPB + e;
    const float* x = X + (size_t)b * 544;

    // dilated convs: u[c][k], c = (d-1)*2 + o
    for (int idx = t; idx < NCAPS * LL; idx += 128) {
        int c = idx / LL, k = idx % LL;
        int d = (c >> 1) + 1, o = c & 1;
        int left = d >> 1;
        const float* w = conv_w + (size_t)((d - 1) * 2 + o) * 4;
        float acc = conv_b[(d - 1) * 2 + o];
        #pragma unroll
        for (int i = 0; i < 2; ++i)
            #pragma unroll
            for (int kk = 0; kk < 2; ++kk) {
                int p = k + kk * d - left;
                if (p >= 0 && p < LL) acc += w[i * 2 + kk] * x[i * LL + p];
            }
        u[e][c][k] = acc;
    }
    __syncthreads();

    // per-capsule norm + squash scale
    if (t < NCAPS) {
        float s2 = 0.f;
        for (int k = 0; k < LL; ++k) { float q = u[e][t][k]; s2 += q * q; }
        float n = sqrtf(s2);
        scale[e][t] = (1.f - 1.f / (expf(n) + 1e-20f)) / (n + 1e-20f);
    }
    __syncthreads();

    // u_hat[c][o] = scale[c] * sum_k W_caps[c,o,k] * u[c,k]
    for (int idx = t; idx < NCAPS * OUTC; idx += 128) {
        int c = idx / OUTC, o = idx % OUTC;
        const float* W = W_caps + ((size_t)c * OUTC + o) * LL;
        float acc = 0.f;
        for (int k = 0; k < LL; ++k) acc += W[k] * u[e][c][k];
        uhat[e][c][o] = acc * scale[e][c];
    }
    __syncthreads();

    // v = squash(sum_c u_hat)
    if (t == 0) {
        float s[OUTC]; float sq = 0.f;
        #pragma unroll
        for (int o = 0; o < OUTC; ++o) {
            float a = 0.f;
            #pragma unroll
            for (int c = 0; c < NCAPS; ++c) a += uhat[e][c][o];
            s[o] = a; sq += a * a;
        }
        float f = sq / (1.f + sq) / sqrtf(sq);
        #pragma unroll
        for (int o = 0; o < OUTC; ++o) vv[e][o] = f * s[o];
    }
    __syncthreads();

    // fc1 (relu) + fc2 partials
    float p0 = 0.f, p1 = 0.f;
    for (int j = t; j < HH; j += 128) {
        float h = fc1_b[j];
        #pragma unroll
        for (int o = 0; o < OUTC; ++o) h += vv[e][o] * fc1_w[j * OUTC + o];
        h = fmaxf(h, 0.f);
        p0 += fc2_w[j] * h;
        p1 += fc2_w[HH + j] * h;
    }
    #pragma unroll
    for (int off = 16; off > 0; off >>= 1) {
        p0 += __shfl_down_sync(0xffffffffu, p0, off);
        p1 += __shfl_down_sync(0xffffffffu, p1, off);
    }
    int lane = t & 31, w = t >> 5;
    if (lane == 0) { wred[e][w][0] = p0; wred[e][w][1] = p1; }
    __syncthreads();

    if (t == 0) {
        float l0 = fc2_b[0], l1 = fc2_b[1];
        #pragma unroll
        for (int ww = 0; ww < 4; ++ww) { l0 += wred[e][ww][0]; l1 += wred[e][ww][1]; }
        out[(size_t)b * 2 + 0] = l0;
        out[(size_t)b * 2 + 1] = l1;
        if (out_size >= 4 * BATCH) {
            float m = fmaxf(l0, l1);
            float e0 = expf(l0 - m), e1 = expf(l1 - m);
            float den = e0 + e1;
            out[(size_t)2 * BATCH + b * 2 + 0] = e0 / den;
            out[(size_t)2 * BATCH + b * 2 + 1] = e1 / den;
        }
    }
}

// ---------------- launch ----------------------------------------------------
extern "C" void kernel_launch(void* const* d_in, const int* in_sizes, int n_in,
                              void* d_out, int out_size)
{
    const int*   seq    = (const int*)  d_in[0];
    const float* sig    = (const float*)d_in[1];
    const float* embed  = (const float*)d_in[2];
    const float* w_ih   = (const float*)d_in[3];   // (3,2,544,272)
    const float* w_hh   = (const float*)d_in[4];   // (3,2,544,136)
    const float* b_ih   = (const float*)d_in[5];   // (3,2,544)
    const float* b_hh   = (const float*)d_in[6];
    const float* conv_w = (const float*)d_in[7];
    const float* conv_b = (const float*)d_in[8];
    const float* W_caps = (const float*)d_in[9];
    const float* fc1_w  = (const float*)d_in[10];
    const float* fc1_b  = (const float*)d_in[11];
    const float* fc2_w  = (const float*)d_in[12];
    const float* fc2_b  = (const float*)d_in[13];
    float* out = (float*)d_out;

    float *X0, *X1, *G, *Cf, *Cb;
    cudaGetSymbolAddress((void**)&X0, g_X0);
    cudaGetSymbolAddress((void**)&X1, g_X1);
    cudaGetSymbolAddress((void**)&G,  g_G);
    cudaGetSymbolAddress((void**)&Cf, g_Cf);
    cudaGetSymbolAddress((void**)&Cb, g_Cb);
    float* Xs[2] = {X0, X1};

    prep_kernel<<<(BATCH * LL + 255) / 256, 256>>>(seq, sig, embed, X0);

    const int cell_blocks = (BATCH * HH + 255) / 256;
    for (int l = 0; l < NL; ++l) {
        float* Xc = Xs[l & 1];
        float* Xn = Xs[(l + 1) & 1];

        // input transform: G(2B,1088) = X(2B,272) @ w_ih[l](1088,272)^T + (b_ih+b_hh)
        dim3 g1((GCOLS + 127) / 128, GROWS / 128);
        sgemm_nt<<<g1, 256>>>(Xc, LL,
                              w_ih + (size_t)l * GCOLS * LL, LL,
                              G, GCOLS,
                              GROWS, GCOLS, LL,
                              b_ih + (size_t)l * GCOLS, b_hh + (size_t)l * GCOLS, 0);

        cell1_kernel<<<cell_blocks, 256>>>(G, Xn, Cf, Cb);

        // recurrent: G[b,t=1,dir0,:] += hf0 @ Wh_f^T ; G[b,t=0,dir1,:] += hb1 @ Wh_b^T
        dim3 g2((GATES + 127) / 128, BATCH / 128);
        sgemm_nt<<<g2, 256>>>(Xn, 544,
                              w_hh + (size_t)(l * 2 + 0) * GATES * HH, HH,
                              G + GCOLS, 2 * GCOLS,
                              BATCH, GATES, HH, nullptr, nullptr, 1);
        sgemm_nt<<<g2, 256>>>(Xn + 408, 544,
                              w_hh + (size_t)(l * 2 + 1) * GATES * HH, HH,
                              G + GATES, 2 * GCOLS,
                              BATCH, GATES, HH, nullptr, nullptr, 1);

        cell2_kernel<<<cell_blocks, 256>>>(G, Xn, Cf, Cb);
    }

    // final activations land in Xs[1] after 3 layers (0->1->0->1)
    head_kernel<<<BATCH / EPB, 128 * EPB>>>(X1, conv_w, conv_b, W_caps,
                                            fc1_w, fc1_b, fc2_w, fc2_b,
                                            out, out_size);
}

// round 3
// speedup vs baseline: 1.3250x; 1.3250x over previous
#include <cuda_runtime.h>
#include <cuda_bf16.h>
#include <mma.h>
#include <cstdint>

using namespace nvcuda;

// ---------------- problem constants ----------------
#define BATCH   16384
#define KMER    17
#define EMB     16
#define HH      136          // hidden
#define LL      272          // input feature dim (= 2*HH)
#define GATES   544          // 4*HH
#define GCOLS   1088         // 2 dirs * 4H
#define GROWS   32768        // 2*BATCH (row = b*2 + t)
#define NL      3
#define OUTC    16
#define NCAPS   10

// ---------------- device scratch (statically allocated) --------------------
__device__ float g_X0[(size_t)BATCH * 2 * LL];
__device__ float g_X1[(size_t)BATCH * 2 * LL];
__device__ float g_G [(size_t)GROWS * GCOLS];
__device__ float g_Cf[(size_t)BATCH * HH];
__device__ float g_Cb[(size_t)BATCH * HH];

// ---------------- prep ------------------------------------------------------
__global__ void prep_kernel(const int* __restrict__ seq,
                            const float* __restrict__ sig,
                            const float* __restrict__ embed,
                            float* __restrict__ X)
{
    int idx = blockIdx.x * blockDim.x + threadIdx.x;
    if (idx >= BATCH * LL) return;
    int b = idx / LL, r = idx % LL;
    int p = r >> 4, e = r & 15;
    int tok = seq[b * KMER + p];
    X[(size_t)b * 544 + r]       = embed[tok * EMB + e];
    X[(size_t)b * 544 + 272 + r] = sig[(size_t)b * LL + r];
}

// ---------------- cp.async helper ------------------------------------------
__device__ __forceinline__ void cp_async16(void* smem, const void* gmem, int srcBytes)
{
    uint32_t s = (uint32_t)__cvta_generic_to_shared(smem);
    asm volatile("cp.async.cg.shared.global [%0], [%1], 16, %2;\n"
                 :: "r"(s), "l"(gmem), "r"(srcBytes));
}

// ---------------- TF32 tensor-core GEMM (NT) --------------------------------
// C[m,n] (+)= sum_k A[m,k]*B[n,k] (+ bias1[n]+bias2[n])
// A:(M,K) rm, B:(N,K) rm. Tiles: 128x128xBK16. 8 warps, warp tile 32x64.
// Requires: M % 128 == 0, N % 16 == 0, K % 4 == 0.
__global__ __launch_bounds__(256)
void gemm_tf32(const float* __restrict__ A, int lda,
               const float* __restrict__ Bm, int ldb,
               float* __restrict__ C, int ldc,
               int M, int N, int K,
               const float* __restrict__ bias1,
               const float* __restrict__ bias2,
               int accumulate)
{
    __shared__ float As[2][128][20];
    __shared__ float Bs[2][128][20];

    const int tid   = threadIdx.x;
    const int warpI = tid >> 5;
    const int lane  = tid & 31;
    const int bm0   = blockIdx.y * 128;
    const int bn0   = blockIdx.x * 128;
    const int wm0   = (warpI & 3) * 32;   // 4 warps along M
    const int wn0   = (warpI >> 2) * 64;  // 2 warps along N

    wmma::fragment<wmma::accumulator, 16, 16, 8, float> acc[2][4];
    #pragma unroll
    for (int i = 0; i < 2; ++i)
        #pragma unroll
        for (int j = 0; j < 4; ++j)
            wmma::fill_fragment(acc[i][j], 0.0f);

    const int nS = (K + 15) >> 4;

    // ---- stage loader (zero-fills K/N overhang) ----
    auto load_stage = [&](int s, int buf) {
        const int k0 = s * 16;
        #pragma unroll
        for (int i = 0; i < 2; ++i) {
            int c   = tid + i * 256;      // 0..511
            int row = c >> 2;             // 0..127
            int kc  = (c & 3) * 4;        // 0,4,8,12
            int kg  = k0 + kc;
            int kok = (kg < K);
            // A tile (rows always < M: M % 128 == 0)
            {
                const float* gp = A + (size_t)(bm0 + row) * lda + (kok ? kg : 0);
                cp_async16(&As[buf][row][kc], gp, kok ? 16 : 0);
            }
            // B tile
            {
                int br  = bn0 + row;
                int bok = (br < N) && kok;
                const float* gp = Bm + (size_t)(br < N ? br : 0) * ldb + (kok ? kg : 0);
                cp_async16(&Bs[buf][row][kc], gp, bok ? 16 : 0);
            }
        }
        asm volatile("cp.async.commit_group;\n");
    };

    load_stage(0, 0);

    for (int s = 0; s < nS; ++s) {
        const int buf = s & 1;
        if (s + 1 < nS) {
            load_stage(s + 1, buf ^ 1);
            asm volatile("cp.async.wait_group 1;\n");
        } else {
            asm volatile("cp.async.wait_group 0;\n");
        }
        __syncthreads();

        #pragma unroll
        for (int ks = 0; ks < 2; ++ks) {
            const int kk = ks * 8;
            wmma::fragment<wmma::matrix_a, 16, 16, 8, wmma::precision::tf32, wmma::row_major> af[2];
            wmma::fragment<wmma::matrix_b, 16, 16, 8, wmma::precision::tf32, wmma::col_major> bf[4];
            #pragma unroll
            for (int i = 0; i < 2; ++i) {
                wmma::load_matrix_sync(af[i], &As[buf][wm0 + i * 16][kk], 20);
                #pragma unroll
                for (int t = 0; t < af[i].num_elements; ++t)
                    af[i].x[t] = wmma::__float_to_tf32(af[i].x[t]);
            }
            #pragma unroll
            for (int j = 0; j < 4; ++j) {
                wmma::load_matrix_sync(bf[j], &Bs[buf][wn0 + j * 16][kk], 20);
                #pragma unroll
                for (int t = 0; t < bf[j].num_elements; ++t)
                    bf[j].x[t] = wmma::__float_to_tf32(bf[j].x[t]);
            }
            #pragma unroll
            for (int i = 0; i < 2; ++i)
                #pragma unroll
                for (int j = 0; j < 4; ++j)
                    wmma::mma_sync(acc[i][j], af[i], bf[j], acc[i][j]);
        }
        __syncthreads();
    }

    // ---- epilogue: stage each 16x16 frag through smem, vectorized store ----
    float* stageW = &As[0][0][0] + warpI * 320;   // 16 x 20 region per warp
    const int rr = lane >> 1;
    const int cc = (lane & 1) * 8;

    #pragma unroll
    for (int i = 0; i < 2; ++i) {
        #pragma unroll
        for (int j = 0; j < 4; ++j) {
            const int cg0 = bn0 + wn0 + j * 16;
            if (cg0 >= N) continue;   // N % 16 == 0 -> frag fully valid or invalid
            wmma::store_matrix_sync(stageW, acc[i][j], 20, wmma::mem_row_major);
            __syncwarp();

            const int gr = bm0 + wm0 + i * 16 + rr;
            const int gc = cg0 + cc;
            float4 v0 = *reinterpret_cast<float4*>(&stageW[rr * 20 + cc]);
            float4 v1 = *reinterpret_cast<float4*>(&stageW[rr * 20 + cc + 4]);
            if (bias1) {
                v0.x += bias1[gc+0] + bias2[gc+0];
                v0.y += bias1[gc+1] + bias2[gc+1];
                v0.z += bias1[gc+2] + bias2[gc+2];
                v0.w += bias1[gc+3] + bias2[gc+3];
                v1.x += bias1[gc+4] + bias2[gc+4];
                v1.y += bias1[gc+5] + bias2[gc+5];
                v1.z += bias1[gc+6] + bias2[gc+6];
                v1.w += bias1[gc+7] + bias2[gc+7];
            }
            float* p = C + (size_t)gr * ldc + gc;
            if (accumulate) {
                float4 o0 = *reinterpret_cast<float4*>(p);
                float4 o1 = *reinterpret_cast<float4*>(p + 4);
                v0.x += o0.x; v0.y += o0.y; v0.z += o0.z; v0.w += o0.w;
                v1.x += o1.x; v1.y += o1.y; v1.z += o1.z; v1.w += o1.w;
            }
            *reinterpret_cast<float4*>(p)     = v0;
            *reinterpret_cast<float4*>(p + 4) = v1;
            __syncwarp();
        }
    }
}

// ---------------- LSTM cells (elementwise) ---------------------------------
__device__ __forceinline__ float sigm(float x) { return 1.f / (1.f + expf(-x)); }

__global__ void cell1_kernel(const float* __restrict__ G,
                             float* __restrict__ Xn,
                             float* __restrict__ Cf,
                             float* __restrict__ Cb)
{
    int idx = blockIdx.x * blockDim.x + threadIdx.x;
    if (idx >= BATCH * HH) return;
    int b = idx / HH, j = idx % HH;

    const float* g = G + (size_t)(2 * b) * GCOLS;             // t=0, dir0
    float c  = sigm(g[j]) * tanhf(g[272 + j]);
    float h  = sigm(g[408 + j]) * tanhf(c);
    Cf[idx] = c;
    Xn[(size_t)b * 544 + j] = h;

    const float* g2 = G + (size_t)(2 * b + 1) * GCOLS + 544;  // t=1, dir1
    float c2 = sigm(g2[j]) * tanhf(g2[272 + j]);
    float h2 = sigm(g2[408 + j]) * tanhf(c2);
    Cb[idx] = c2;
    Xn[(size_t)b * 544 + 408 + j] = h2;
}

__global__ void cell2_kernel(const float* __restrict__ G,
                             float* __restrict__ Xn,
                             const float* __restrict__ Cf,
                             const float* __restrict__ Cb)
{
    int idx = blockIdx.x * blockDim.x + threadIdx.x;
    if (idx >= BATCH * HH) return;
    int b = idx / HH, j = idx % HH;

    const float* g = G + (size_t)(2 * b + 1) * GCOLS;         // t=1, dir0
    float c  = sigm(g[136 + j]) * Cf[idx] + sigm(g[j]) * tanhf(g[272 + j]);
    float h  = sigm(g[408 + j]) * tanhf(c);
    Xn[(size_t)b * 544 + 272 + j] = h;

    const float* g2 = G + (size_t)(2 * b) * GCOLS + 544;      // t=0, dir1
    float c2 = sigm(g2[136 + j]) * Cb[idx] + sigm(g2[j]) * tanhf(g2[272 + j]);
    float h2 = sigm(g2[408 + j]) * tanhf(c2);
    Xn[(size_t)b * 544 + 136 + j] = h2;
}

// ---------------- fused head ------------------------------------------------
#define EPB 2
__global__ __launch_bounds__(128 * EPB)
void head_kernel(const float* __restrict__ X,
                 const float* __restrict__ conv_w,
                 const float* __restrict__ conv_b,
                 const float* __restrict__ W_caps,
                 const float* __restrict__ fc1_w,
                 const float* __restrict__ fc1_b,
                 const float* __restrict__ fc2_w,
                 const float* __restrict__ fc2_b,
                 float* __restrict__ out, int out_size)
{
    __shared__ float u[EPB][NCAPS][LL];
    __shared__ float scale[EPB][NCAPS];
    __shared__ float uhat[EPB][NCAPS][OUTC];
    __shared__ float vv[EPB][OUTC];
    __shared__ float wred[EPB][4][2];

    const int e = threadIdx.x >> 7;
    const int t = threadIdx.x & 127;
    const int b = blockIdx.x * EPB + e;
    const float* x = X + (size_t)b * 544;

    for (int idx = t; idx < NCAPS * LL; idx += 128) {
        int c = idx / LL, k = idx % LL;
        int d = (c >> 1) + 1, o = c & 1;
        int left = d >> 1;
        const float* w = conv_w + (size_t)((d - 1) * 2 + o) * 4;
        float acc = conv_b[(d - 1) * 2 + o];
        #pragma unroll
        for (int i = 0; i < 2; ++i)
            #pragma unroll
            for (int kk = 0; kk < 2; ++kk) {
                int p = k + kk * d - left;
                if (p >= 0 && p < LL) acc += w[i * 2 + kk] * x[i * LL + p];
            }
        u[e][c][k] = acc;
    }
    __syncthreads();

    if (t < NCAPS) {
        float s2 = 0.f;
        for (int k = 0; k < LL; ++k) { float q = u[e][t][k]; s2 += q * q; }
        float n = sqrtf(s2);
        scale[e][t] = (1.f - 1.f / (expf(n) + 1e-20f)) / (n + 1e-20f);
    }
    __syncthreads();

    for (int idx = t; idx < NCAPS * OUTC; idx += 128) {
        int c = idx / OUTC, o = idx % OUTC;
        const float* W = W_caps + ((size_t)c * OUTC + o) * LL;
        float acc = 0.f;
        for (int k = 0; k < LL; ++k) acc += W[k] * u[e][c][k];
        uhat[e][c][o] = acc * scale[e][c];
    }
    __syncthreads();

    if (t == 0) {
        float s[OUTC]; float sq = 0.f;
        #pragma unroll
        for (int o = 0; o < OUTC; ++o) {
            float a = 0.f;
            #pragma unroll
            for (int c = 0; c < NCAPS; ++c) a += uhat[e][c][o];
            s[o] = a; sq += a * a;
        }
        float f = sq / (1.f + sq) / sqrtf(sq);
        #pragma unroll
        for (int o = 0; o < OUTC; ++o) vv[e][o] = f * s[o];
    }
    __syncthreads();

    float p0 = 0.f, p1 = 0.f;
    for (int j = t; j < HH; j += 128) {
        float h = fc1_b[j];
        #pragma unroll
        for (int o = 0; o < OUTC; ++o) h += vv[e][o] * fc1_w[j * OUTC + o];
        h = fmaxf(h, 0.f);
        p0 += fc2_w[j] * h;
        p1 += fc2_w[HH + j] * h;
    }
    #pragma unroll
    for (int off = 16; off > 0; off >>= 1) {
        p0 += __shfl_down_sync(0xffffffffu, p0, off);
        p1 += __shfl_down_sync(0xffffffffu, p1, off);
    }
    int lane = t & 31, w = t >> 5;
    if (lane == 0) { wred[e][w][0] = p0; wred[e][w][1] = p1; }
    __syncthreads();

    if (t == 0) {
        float l0 = fc2_b[0], l1 = fc2_b[1];
        #pragma unroll
        for (int ww = 0; ww < 4; ++ww) { l0 += wred[e][ww][0]; l1 += wred[e][ww][1]; }
        out[(size_t)b * 2 + 0] = l0;
        out[(size_t)b * 2 + 1] = l1;
        if (out_size >= 4 * BATCH) {
            float m = fmaxf(l0, l1);
            float e0 = expf(l0 - m), e1 = expf(l1 - m);
            float den = e0 + e1;
            out[(size_t)2 * BATCH + b * 2 + 0] = e0 / den;
            out[(size_t)2 * BATCH + b * 2 + 1] = e1 / den;
        }
    }
}

// ---------------- launch ----------------------------------------------------
extern "C" void kernel_launch(void* const* d_in, const int* in_sizes, int n_in,
                              void* d_out, int out_size)
{
    const int*   seq    = (const int*)  d_in[0];
    const float* sig    = (const float*)d_in[1];
    const float* embed  = (const float*)d_in[2];
    const float* w_ih   = (const float*)d_in[3];
    const float* w_hh   = (const float*)d_in[4];
    const float* b_ih   = (const float*)d_in[5];
    const float* b_hh   = (const float*)d_in[6];
    const float* conv_w = (const float*)d_in[7];
    const float* conv_b = (const float*)d_in[8];
    const float* W_caps = (const float*)d_in[9];
    const float* fc1_w  = (const float*)d_in[10];
    const float* fc1_b  = (const float*)d_in[11];
    const float* fc2_w  = (const float*)d_in[12];
    const float* fc2_b  = (const float*)d_in[13];
    float* out = (float*)d_out;

    float *X0, *X1, *G, *Cf, *Cb;
    cudaGetSymbolAddress((void**)&X0, g_X0);
    cudaGetSymbolAddress((void**)&X1, g_X1);
    cudaGetSymbolAddress((void**)&G,  g_G);
    cudaGetSymbolAddress((void**)&Cf, g_Cf);
    cudaGetSymbolAddress((void**)&Cb, g_Cb);
    float* Xs[2] = {X0, X1};

    prep_kernel<<<(BATCH * LL + 255) / 256, 256>>>(seq, sig, embed, X0);

    const int cell_blocks = (BATCH * HH + 255) / 256;
    for (int l = 0; l < NL; ++l) {
        float* Xc = Xs[l & 1];
        float* Xn = Xs[(l + 1) & 1];

        // input transform: G(2B,1088) = X(2B,272) @ w_ih[l]^T + (b_ih+b_hh)
        dim3 g1((GCOLS + 127) / 128, GROWS / 128);
        gemm_tf32<<<g1, 256>>>(Xc, LL,
                               w_ih + (size_t)l * GCOLS * LL, LL,
                               G, GCOLS,
                               GROWS, GCOLS, LL,
                               b_ih + (size_t)l * GCOLS, b_hh + (size_t)l * GCOLS, 0);

        cell1_kernel<<<cell_blocks, 256>>>(G, Xn, Cf, Cb);

        dim3 g2((GATES + 127) / 128, BATCH / 128);
        gemm_tf32<<<g2, 256>>>(Xn, 544,
                               w_hh + (size_t)(l * 2 + 0) * GATES * HH, HH,
                               G + GCOLS, 2 * GCOLS,
                               BATCH, GATES, HH, nullptr, nullptr, 1);
        gemm_tf32<<<g2, 256>>>(Xn + 408, 544,
                               w_hh + (size_t)(l * 2 + 1) * GATES * HH, HH,
                               G + GATES, 2 * GCOLS,
                               BATCH, GATES, HH, nullptr, nullptr, 1);

        cell2_kernel<<<cell_blocks, 256>>>(G, Xn, Cf, Cb);
    }

    head_kernel<<<BATCH / EPB, 128 * EPB>>>(X1, conv_w, conv_b, W_caps,
                                            fc1_w, fc1_b, fc2_w, fc2_b,
                                            out, out_size);
}

// round 4
// speedup vs baseline: 1.8084x; 1.3648x over previous
#include <cuda_runtime.h>
#include <cuda_bf16.h>
#include <mma.h>
#include <cstdint>

using namespace nvcuda;

// ---------------- problem constants ----------------
#define BATCH   16384
#define KMER    17
#define EMB     16
#define HH      136          // hidden
#define LL      272          // input feature dim (= 2*HH)
#define GATES   544          // 4*HH
#define GCOLS   1088         // 2 dirs * 4H
#define GROWS   32768        // 2*BATCH (row = b*2 + t)
#define NL      3
#define OUTC    16
#define NCAPS   10

// ---------------- device scratch (statically allocated) --------------------
__device__ __nv_bfloat16 g_Xb0[(size_t)BATCH * 2 * LL];
__device__ __nv_bfloat16 g_Xb1[(size_t)BATCH * 2 * LL];
__device__ float         g_G  [(size_t)GROWS * GCOLS];
__device__ float         g_Cf [(size_t)BATCH * HH];
__device__ float         g_Cb [(size_t)BATCH * HH];
__device__ __nv_bfloat16 g_Wih[(size_t)NL * GCOLS * LL];
__device__ __nv_bfloat16 g_Whh[(size_t)NL * 2 * GATES * HH];

// ---------------- weight conversion ----------------------------------------
__global__ void convert_weights(const float* __restrict__ wih,
                                const float* __restrict__ whh,
                                __nv_bfloat16* __restrict__ wihb,
                                __nv_bfloat16* __restrict__ whhb)
{
    int i = blockIdx.x * blockDim.x + threadIdx.x;
    const int nIH = NL * GCOLS * LL;       // 887808
    const int nHH = NL * 2 * GATES * HH;   // 443904
    if (i < nIH) wihb[i] = __float2bfloat16(wih[i]);
    if (i < nHH) whhb[i] = __float2bfloat16(whh[i]);
}

// ---------------- prep: build layer-0 input (bf16) --------------------------
__global__ void prep_kernel(const int* __restrict__ seq,
                            const float* __restrict__ sig,
                            const float* __restrict__ embed,
                            __nv_bfloat16* __restrict__ X)
{
    int idx = blockIdx.x * blockDim.x + threadIdx.x;
    if (idx >= BATCH * LL) return;
    int b = idx / LL, r = idx % LL;
    int p = r >> 4, e = r & 15;
    int tok = seq[b * KMER + p];
    X[(size_t)b * 544 + r]       = __float2bfloat16(embed[tok * EMB + e]);
    X[(size_t)b * 544 + 272 + r] = __float2bfloat16(sig[(size_t)b * LL + r]);
}

// ---------------- cp.async helper ------------------------------------------
__device__ __forceinline__ void cp_async16(void* smem, const void* gmem, int srcBytes)
{
    uint32_t s = (uint32_t)__cvta_generic_to_shared(smem);
    asm volatile("cp.async.cg.shared.global [%0], [%1], 16, %2;\n"
                 :: "r"(s), "l"(gmem), "r"(srcBytes));
}

// ---------------- bf16 tensor-core GEMM (NT) ---------------------------------
// C[m,n] (+)= sum_k A[m,k]*B[n,k] (+ bias1[n]+bias2[n]); fp32 accumulate.
// A:(M,K) bf16 rm, B:(N,K) bf16 rm. 128x128 block tile, BK=32, 8 warps (32x64 each).
// blockIdx.z selects a direction: pointers advance by aOff/bOff/cOff elements.
// Requires: M % 128 == 0, N % 16 == 0, K % 8 == 0.
__global__ __launch_bounds__(256)
void gemm_bf16(const __nv_bfloat16* __restrict__ A, int lda, long long aOff,
               const __nv_bfloat16* __restrict__ Bm, int ldb, long long bOff,
               float* __restrict__ C, int ldc, long long cOff,
               int M, int N, int K,
               const float* __restrict__ bias1,
               const float* __restrict__ bias2,
               int accumulate)
{
    __shared__ __align__(16) char smraw[2 * 128 * 40 * 2 * 2];   // 40960 B
    typedef __nv_bfloat16 tileT[128][40];
    tileT* As = reinterpret_cast<tileT*>(smraw);                  // As[2][128][40]
    tileT* Bs = reinterpret_cast<tileT*>(smraw + 20480);          // Bs[2][128][40]

    A  += (long long)blockIdx.z * aOff;
    Bm += (long long)blockIdx.z * bOff;
    C  += (long long)blockIdx.z * cOff;

    const int tid   = threadIdx.x;
    const int warpI = tid >> 5;
    const int lane  = tid & 31;
    const int bm0   = blockIdx.y * 128;
    const int bn0   = blockIdx.x * 128;
    const int wm0   = (warpI & 3) * 32;   // 4 warps along M
    const int wn0   = (warpI >> 2) * 64;  // 2 warps along N

    wmma::fragment<wmma::accumulator, 16, 16, 16, float> acc[2][4];
    #pragma unroll
    for (int i = 0; i < 2; ++i)
        #pragma unroll
        for (int j = 0; j < 4; ++j)
            wmma::fill_fragment(acc[i][j], 0.0f);

    const int nS = (K + 31) >> 5;

    auto load_stage = [&](int s, int buf) {
        const int k0 = s * 32;
        #pragma unroll
        for (int i = 0; i < 2; ++i) {
            int c   = tid + i * 256;      // 0..511
            int row = c >> 2;             // 0..127
            int kc  = (c & 3) * 8;        // 0,8,16,24
            int kg  = k0 + kc;
            bool kok = (kg < K);
            {   // A tile: rows always valid (M % 128 == 0)
                const __nv_bfloat16* gp = A + (size_t)(bm0 + row) * lda + (kok ? kg : 0);
                cp_async16(&As[buf][row][kc], gp, kok ? 16 : 0);
            }
            {   // B tile
                int br   = bn0 + row;
                bool ok  = kok && (br < N);
                const __nv_bfloat16* gp = Bm + (size_t)(ok ? br : 0) * ldb + (kok ? kg : 0);
                cp_async16(&Bs[buf][row][kc], gp, ok ? 16 : 0);
            }
        }
        asm volatile("cp.async.commit_group;\n");
    };

    load_stage(0, 0);

    for (int s = 0; s < nS; ++s) {
        const int buf = s & 1;
        if (s + 1 < nS) {
            load_stage(s + 1, buf ^ 1);
            asm volatile("cp.async.wait_group 1;\n");
        } else {
            asm volatile("cp.async.wait_group 0;\n");
        }
        __syncthreads();

        #pragma unroll
        for (int ks = 0; ks < 2; ++ks) {
            const int kk = ks * 16;
            wmma::fragment<wmma::matrix_a, 16, 16, 16, __nv_bfloat16, wmma::row_major> af[2];
            wmma::fragment<wmma::matrix_b, 16, 16, 16, __nv_bfloat16, wmma::col_major> bfr[4];
            #pragma unroll
            for (int i = 0; i < 2; ++i)
                wmma::load_matrix_sync(af[i], &As[buf][wm0 + i * 16][kk], 40);
            #pragma unroll
            for (int j = 0; j < 4; ++j)
                wmma::load_matrix_sync(bfr[j], &Bs[buf][wn0 + j * 16][kk], 40);
            #pragma unroll
            for (int i = 0; i < 2; ++i)
                #pragma unroll
                for (int j = 0; j < 4; ++j)
                    wmma::mma_sync(acc[i][j], af[i], bfr[j], acc[i][j]);
        }
        __syncthreads();
    }

    // ---- epilogue: stage each 16x16 frag through smem, vectorized store ----
    float* stageW = reinterpret_cast<float*>(smraw) + warpI * 320;  // 16x20 per warp
    const int rr = lane >> 1;
    const int cc = (lane & 1) * 8;

    #pragma unroll
    for (int i = 0; i < 2; ++i) {
        #pragma unroll
        for (int j = 0; j < 4; ++j) {
            const int cg0 = bn0 + wn0 + j * 16;
            if (cg0 >= N) continue;   // N % 16 == 0 -> frag fully valid or invalid
            wmma::store_matrix_sync(stageW, acc[i][j], 20, wmma::mem_row_major);
            __syncwarp();

            const int gr = bm0 + wm0 + i * 16 + rr;
            const int gc = cg0 + cc;
            float4 v0 = *reinterpret_cast<float4*>(&stageW[rr * 20 + cc]);
            float4 v1 = *reinterpret_cast<float4*>(&stageW[rr * 20 + cc + 4]);
            if (bias1) {
                v0.x += bias1[gc+0] + bias2[gc+0];
                v0.y += bias1[gc+1] + bias2[gc+1];
                v0.z += bias1[gc+2] + bias2[gc+2];
                v0.w += bias1[gc+3] + bias2[gc+3];
                v1.x += bias1[gc+4] + bias2[gc+4];
                v1.y += bias1[gc+5] + bias2[gc+5];
                v1.z += bias1[gc+6] + bias2[gc+6];
                v1.w += bias1[gc+7] + bias2[gc+7];
            }
            float* p = C + (size_t)gr * ldc + gc;
            if (accumulate) {
                float4 o0 = *reinterpret_cast<float4*>(p);
                float4 o1 = *reinterpret_cast<float4*>(p + 4);
                v0.x += o0.x; v0.y += o0.y; v0.z += o0.z; v0.w += o0.w;
                v1.x += o1.x; v1.y += o1.y; v1.z += o1.z; v1.w += o1.w;
            }
            *reinterpret_cast<float4*>(p)     = v0;
            *reinterpret_cast<float4*>(p + 4) = v1;
            __syncwarp();
        }
    }
}

// ---------------- LSTM cells (elementwise, bf16 activations out) ------------
__device__ __forceinline__ float sigm(float x) { return 1.f / (1.f + expf(-x)); }

__global__ void cell1_kernel(const float* __restrict__ G,
                             __nv_bfloat16* __restrict__ Xn,
                             float* __restrict__ Cf,
                             float* __restrict__ Cb)
{
    int idx = blockIdx.x * blockDim.x + threadIdx.x;
    if (idx >= BATCH * HH) return;
    int b = idx / HH, j = idx % HH;

    const float* g = G + (size_t)(2 * b) * GCOLS;             // t=0, dir0
    float c  = sigm(g[j]) * tanhf(g[272 + j]);
    float h  = sigm(g[408 + j]) * tanhf(c);
    Cf[idx] = c;
    Xn[(size_t)b * 544 + j] = __float2bfloat16(h);            // hf0 -> x[b,0,0:136]

    const float* g2 = G + (size_t)(2 * b + 1) * GCOLS + 544;  // t=1, dir1
    float c2 = sigm(g2[j]) * tanhf(g2[272 + j]);
    float h2 = sigm(g2[408 + j]) * tanhf(c2);
    Cb[idx] = c2;
    Xn[(size_t)b * 544 + 408 + j] = __float2bfloat16(h2);     // hb1 -> x[b,1,136:272]
}

__global__ void cell2_kernel(const float* __restrict__ G,
                             __nv_bfloat16* __restrict__ Xn,
                             const float* __restrict__ Cf,
                             const float* __restrict__ Cb)
{
    int idx = blockIdx.x * blockDim.x + threadIdx.x;
    if (idx >= BATCH * HH) return;
    int b = idx / HH, j = idx % HH;

    const float* g = G + (size_t)(2 * b + 1) * GCOLS;         // t=1, dir0
    float c  = sigm(g[136 + j]) * Cf[idx] + sigm(g[j]) * tanhf(g[272 + j]);
    float h  = sigm(g[408 + j]) * tanhf(c);
    Xn[(size_t)b * 544 + 272 + j] = __float2bfloat16(h);      // hf1 -> x[b,1,0:136]

    const float* g2 = G + (size_t)(2 * b) * GCOLS + 544;      // t=0, dir1
    float c2 = sigm(g2[136 + j]) * Cb[idx] + sigm(g2[j]) * tanhf(g2[272 + j]);
    float h2 = sigm(g2[408 + j]) * tanhf(c2);
    Xn[(size_t)b * 544 + 136 + j] = __float2bfloat16(h2);     // hb0 -> x[b,0,136:272]
}

// ---------------- fused head (reads bf16 activations) -----------------------
#define EPB 2
__global__ __launch_bounds__(128 * EPB)
void head_kernel(const __nv_bfloat16* __restrict__ X,
                 const float* __restrict__ conv_w,
                 const float* __restrict__ conv_b,
                 const float* __restrict__ W_caps,
                 const float* __restrict__ fc1_w,
                 const float* __restrict__ fc1_b,
                 const float* __restrict__ fc2_w,
                 const float* __restrict__ fc2_b,
                 float* __restrict__ out, int out_size)
{
    __shared__ float u[EPB][NCAPS][LL];
    __shared__ float xs[EPB][2][LL];
    __shared__ float scale[EPB][NCAPS];
    __shared__ float uhat[EPB][NCAPS][OUTC];
    __shared__ float vv[EPB][OUTC];
    __shared__ float wred[EPB][4][2];

    const int e = threadIdx.x >> 7;
    const int t = threadIdx.x & 127;
    const int b = blockIdx.x * EPB + e;
    const __nv_bfloat16* x = X + (size_t)b * 544;

    // stage x into smem as fp32
    for (int i = t; i < 544; i += 128)
        xs[e][i / LL][i % LL] = __bfloat162float(x[i]);
    __syncthreads();

    for (int idx = t; idx < NCAPS * LL; idx += 128) {
        int c = idx / LL, k = idx % LL;
        int d = (c >> 1) + 1, o = c & 1;
        int left = d >> 1;
        const float* w = conv_w + (size_t)((d - 1) * 2 + o) * 4;
        float acc = conv_b[(d - 1) * 2 + o];
        #pragma unroll
        for (int i = 0; i < 2; ++i)
            #pragma unroll
            for (int kk = 0; kk < 2; ++kk) {
                int p = k + kk * d - left;
                if (p >= 0 && p < LL) acc += w[i * 2 + kk] * xs[e][i][p];
            }
        u[e][c][k] = acc;
    }
    __syncthreads();

    if (t < NCAPS) {
        float s2 = 0.f;
        for (int k = 0; k < LL; ++k) { float q = u[e][t][k]; s2 += q * q; }
        float n = sqrtf(s2);
        scale[e][t] = (1.f - 1.f / (expf(n) + 1e-20f)) / (n + 1e-20f);
    }
    __syncthreads();

    for (int idx = t; idx < NCAPS * OUTC; idx += 128) {
        int c = idx / OUTC, o = idx % OUTC;
        const float* W = W_caps + ((size_t)c * OUTC + o) * LL;
        float acc = 0.f;
        for (int k = 0; k < LL; ++k) acc += W[k] * u[e][c][k];
        uhat[e][c][o] = acc * scale[e][c];
    }
    __syncthreads();

    if (t == 0) {
        float s[OUTC]; float sq = 0.f;
        #pragma unroll
        for (int o = 0; o < OUTC; ++o) {
            float a = 0.f;
            #pragma unroll
            for (int c = 0; c < NCAPS; ++c) a += uhat[e][c][o];
            s[o] = a; sq += a * a;
        }
        float f = sq / (1.f + sq) / sqrtf(sq);
        #pragma unroll
        for (int o = 0; o < OUTC; ++o) vv[e][o] = f * s[o];
    }
    __syncthreads();

    float p0 = 0.f, p1 = 0.f;
    for (int j = t; j < HH; j += 128) {
        float h = fc1_b[j];
        #pragma unroll
        for (int o = 0; o < OUTC; ++o) h += vv[e][o] * fc1_w[j * OUTC + o];
        h = fmaxf(h, 0.f);
        p0 += fc2_w[j] * h;
        p1 += fc2_w[HH + j] * h;
    }
    #pragma unroll
    for (int off = 16; off > 0; off >>= 1) {
        p0 += __shfl_down_sync(0xffffffffu, p0, off);
        p1 += __shfl_down_sync(0xffffffffu, p1, off);
    }
    int lane = t & 31, w = t >> 5;
    if (lane == 0) { wred[e][w][0] = p0; wred[e][w][1] = p1; }
    __syncthreads();

    if (t == 0) {
        float l0 = fc2_b[0], l1 = fc2_b[1];
        #pragma unroll
        for (int ww = 0; ww < 4; ++ww) { l0 += wred[e][ww][0]; l1 += wred[e][ww][1]; }
        out[(size_t)b * 2 + 0] = l0;
        out[(size_t)b * 2 + 1] = l1;
        if (out_size >= 4 * BATCH) {
            float m = fmaxf(l0, l1);
            float e0 = expf(l0 - m), e1 = expf(l1 - m);
            float den = e0 + e1;
            out[(size_t)2 * BATCH + b * 2 + 0] = e0 / den;
            out[(size_t)2 * BATCH + b * 2 + 1] = e1 / den;
        }
    }
}

// ---------------- launch ----------------------------------------------------
extern "C" void kernel_launch(void* const* d_in, const int* in_sizes, int n_in,
                              void* d_out, int out_size)
{
    const int*   seq    = (const int*)  d_in[0];
    const float* sig    = (const float*)d_in[1];
    const float* embed  = (const float*)d_in[2];
    const float* w_ih   = (const float*)d_in[3];
    const float* w_hh   = (const float*)d_in[4];
    const float* b_ih   = (const float*)d_in[5];
    const float* b_hh   = (const float*)d_in[6];
    const float* conv_w = (const float*)d_in[7];
    const float* conv_b = (const float*)d_in[8];
    const float* W_caps = (const float*)d_in[9];
    const float* fc1_w  = (const float*)d_in[10];
    const float* fc1_b  = (const float*)d_in[11];
    const float* fc2_w  = (const float*)d_in[12];
    const float* fc2_b  = (const float*)d_in[13];
    float* out = (float*)d_out;

    __nv_bfloat16 *X0, *X1, *Wih, *Whh;
    float *G, *Cf, *Cb;
    cudaGetSymbolAddress((void**)&X0,  g_Xb0);
    cudaGetSymbolAddress((void**)&X1,  g_Xb1);
    cudaGetSymbolAddress((void**)&G,   g_G);
    cudaGetSymbolAddress((void**)&Cf,  g_Cf);
    cudaGetSymbolAddress((void**)&Cb,  g_Cb);
    cudaGetSymbolAddress((void**)&Wih, g_Wih);
    cudaGetSymbolAddress((void**)&Whh, g_Whh);
    __nv_bfloat16* Xs[2] = {X0, X1};

    const int nIH = NL * GCOLS * LL;
    convert_weights<<<(nIH + 255) / 256, 256>>>(w_ih, w_hh, Wih, Whh);
    prep_kernel<<<(BATCH * LL + 255) / 256, 256>>>(seq, sig, embed, X0);

    const int cell_blocks = (BATCH * HH + 255) / 256;
    for (int l = 0; l < NL; ++l) {
        __nv_bfloat16* Xc = Xs[l & 1];
        __nv_bfloat16* Xn = Xs[(l + 1) & 1];

        // input transform: G(2B,1088) = X(2B,272) @ w_ih[l]^T + (b_ih+b_hh)
        dim3 g1((GCOLS + 127) / 128, GROWS / 128, 1);
        gemm_bf16<<<g1, 256>>>(Xc, LL, 0,
                               Wih + (size_t)l * GCOLS * LL, LL, 0,
                               G, GCOLS, 0,
                               GROWS, GCOLS, LL,
                               b_ih + (size_t)l * GCOLS, b_hh + (size_t)l * GCOLS, 0);

        cell1_kernel<<<cell_blocks, 256>>>(G, Xn, Cf, Cb);

        // recurrent (both directions in one launch via blockIdx.z):
        //  z=0: G[b,t=1,dir0,:] += hf0 @ Wh_f^T   (A=Xn,     C=G+GCOLS)
        //  z=1: G[b,t=0,dir1,:] += hb1 @ Wh_b^T   (A=Xn+408, C=G+GATES)
        dim3 g2((GATES + 127) / 128, BATCH / 128, 2);
        gemm_bf16<<<g2, 256>>>(Xn, 544, 408,
                               Whh + (size_t)(l * 2) * GATES * HH, HH, (long long)GATES * HH,
                               G + GCOLS, 2 * GCOLS, (long long)GATES - GCOLS,
                               BATCH, GATES, HH, nullptr, nullptr, 1);

        cell2_kernel<<<cell_blocks, 256>>>(G, Xn, Cf, Cb);
    }

    head_kernel<<<BATCH / EPB, 128 * EPB>>>(X1, conv_w, conv_b, W_caps,
                                            fc1_w, fc1_b, fc2_w, fc2_b,
                                            out, out_size);
}

// round 6
// speedup vs baseline: 1.8824x; 1.0409x over previous
#include <cuda_runtime.h>
#include <cuda_bf16.h>
#include <mma.h>
#include <cstdint>

using namespace nvcuda;

// ---------------- problem constants ----------------
#define BATCH   16384
#define KMER    17
#define EMB     16
#define HH      136          // hidden
#define LL      272          // input feature dim (= 2*HH)
#define GATES   544          // 4*HH
#define GCOLS   1088         // 2 dirs * 4H
#define GROWS   32768        // 2*BATCH (row = b*2 + t)
#define NL      3
#define OUTC    16
#define NCAPS   10

// ---------------- device scratch (statically allocated) --------------------
__device__ __nv_bfloat16 g_Xb0[(size_t)BATCH * 2 * LL];
__device__ __nv_bfloat16 g_Xb1[(size_t)BATCH * 2 * LL];
__device__ float         g_G  [(size_t)GROWS * GCOLS];
__device__ float         g_Cf [(size_t)BATCH * HH];
__device__ float         g_Cb [(size_t)BATCH * HH];
__device__ __nv_bfloat16 g_Wih[(size_t)NL * GCOLS * LL];
__device__ __nv_bfloat16 g_Whh[(size_t)NL * 2 * GATES * HH];
__device__ float         g_Bs [(size_t)NL * GCOLS];

__device__ __forceinline__ float sigm(float x) { return 1.f / (1.f + expf(-x)); }

// ---------------- weight conversion + gate permutation ----------------------
// Permutation: within each direction, output col n_perm = 4*j + g  maps from
// original row g*136 + j  (g in {i,f,g,o}). So a float4 at col 4j is (i,f,g,o)_j.
__global__ void convert_weights(const float* __restrict__ wih,
                                const float* __restrict__ whh,
                                const float* __restrict__ bih,
                                const float* __restrict__ bhh,
                                __nv_bfloat16* __restrict__ wihb,
                                __nv_bfloat16* __restrict__ whhb,
                                float* __restrict__ bsum)
{
    int i = blockIdx.x * blockDim.x + threadIdx.x;
    const int nIH = NL * GCOLS * LL;
    const int nHH = NL * 2 * GATES * HH;
    const int nB  = NL * GCOLS;
    if (i < nIH) {
        int l = i / (GCOLS * LL); int r = i % (GCOLS * LL);
        int np = r / LL, k = r % LL;
        int d = np / GATES, q = np % GATES;
        int j = q >> 2, g = q & 3;
        wihb[i] = __float2bfloat16(wih[((size_t)(l * 2 + d) * GATES + g * HH + j) * LL + k]);
    }
    if (i < nHH) {
        int l = i / (2 * GATES * HH); int r = i % (2 * GATES * HH);
        int d = r / (GATES * HH); int r2 = r % (GATES * HH);
        int np = r2 / HH, k = r2 % HH;
        int j = np >> 2, g = np & 3;
        whhb[i] = __float2bfloat16(whh[((size_t)(l * 2 + d) * GATES + g * HH + j) * HH + k]);
    }
    if (i < nB) {
        int l = i / GCOLS; int np = i % GCOLS;
        int d = np / GATES, q = np % GATES;
        int j = q >> 2, g = q & 3;
        int src = (l * 2 + d) * GATES + g * HH + j;
        bsum[i] = bih[src] + bhh[src];
    }
}

// ---------------- prep: build layer-0 input (bf16) --------------------------
__global__ void prep_kernel(const int* __restrict__ seq,
                            const float* __restrict__ sig,
                            const float* __restrict__ embed,
                            __nv_bfloat16* __restrict__ X)
{
    int idx = blockIdx.x * blockDim.x + threadIdx.x;
    if (idx >= BATCH * LL) return;
    int b = idx / LL, r = idx % LL;
    int p = r >> 4, e = r & 15;
    int tok = seq[b * KMER + p];
    X[(size_t)b * 544 + r]       = __float2bfloat16(embed[tok * EMB + e]);
    X[(size_t)b * 544 + 272 + r] = __float2bfloat16(sig[(size_t)b * LL + r]);
}

// ---------------- cp.async helper ------------------------------------------
__device__ __forceinline__ void cp_async16(void* smem, const void* gmem, int srcBytes)
{
    uint32_t s = (uint32_t)__cvta_generic_to_shared(smem);
    asm volatile("cp.async.cg.shared.global [%0], [%1], 16, %2;\n"
                 :: "r"(s), "l"(gmem), "r"(srcBytes));
}

// ---------------- fused bf16 GEMM (NT) ---------------------------------------
// MODE 0 (input transform + cell1):
//   raw[m,n] = sum_k Xc[m,k]*Wih[n,k] + bsum[n]        (m = 2b+t, n = dir*544+4j+g)
//   if (t == dir): activate first step -> Cf/Cb[b,j], Xn h slot; else G[m,n] = raw.
// MODE 1 (recurrent + cell2), z = blockIdx.z = direction:
//   acc[b,n] = sum_k h_first[b,k]*Whh[n,k];  v = acc + G[2b+1-z, z*544+n]
//   cell2 with Cf/Cb -> Xn h slot.   (G is not written)
template<int MODE>
__global__ __launch_bounds__(256)
void gemm_fused(const __nv_bfloat16* __restrict__ A, int lda, long long aOff,
                const __nv_bfloat16* __restrict__ Bm, int ldb, long long bOff,
                float* __restrict__ G,
                const float* __restrict__ bsum,
                __nv_bfloat16* __restrict__ Xn,
                float* __restrict__ Cf,
                float* __restrict__ Cb,
                int M, int N, int K)
{
    __shared__ __align__(16) char smraw[2 * 128 * 40 * 2 * 2];   // 40960 B
    typedef __nv_bfloat16 tileT[128][40];
    tileT* As = reinterpret_cast<tileT*>(smraw);
    tileT* Bs = reinterpret_cast<tileT*>(smraw + 20480);

    const int z = blockIdx.z;
    A  += (long long)z * aOff;
    Bm += (long long)z * bOff;

    const int tid   = threadIdx.x;
    const int warpI = tid >> 5;
    const int lane  = tid & 31;
    const int bm0   = blockIdx.y * 128;
    const int bn0   = blockIdx.x * 128;
    const int wm0   = (warpI & 3) * 32;
    const int wn0   = (warpI >> 2) * 64;

    wmma::fragment<wmma::accumulator, 16, 16, 16, float> acc[2][4];
    #pragma unroll
    for (int i = 0; i < 2; ++i)
        #pragma unroll
        for (int j = 0; j < 4; ++j)
            wmma::fill_fragment(acc[i][j], 0.0f);

    const int nS = (K + 31) >> 5;

    auto load_stage = [&](int s, int buf) {
        const int k0 = s * 32;
        #pragma unroll
        for (int i = 0; i < 2; ++i) {
            int c   = tid + i * 256;
            int row = c >> 2;
            int kc  = (c & 3) * 8;
            int kg  = k0 + kc;
            bool kok = (kg < K);
            {
                const __nv_bfloat16* gp = A + (size_t)(bm0 + row) * lda + (kok ? kg : 0);
                cp_async16(&As[buf][row][kc], gp, kok ? 16 : 0);
            }
            {
                int br  = bn0 + row;
                bool ok = kok && (br < N);
                const __nv_bfloat16* gp = Bm + (size_t)(ok ? br : 0) * ldb + (kok ? kg : 0);
                cp_async16(&Bs[buf][row][kc], gp, ok ? 16 : 0);
            }
        }
        asm volatile("cp.async.commit_group;\n");
    };

    load_stage(0, 0);

    for (int s = 0; s < nS; ++s) {
        const int buf = s & 1;
        if (s + 1 < nS) {
            load_stage(s + 1, buf ^ 1);
            asm volatile("cp.async.wait_group 1;\n");
        } else {
            asm volatile("cp.async.wait_group 0;\n");
        }
        __syncthreads();

        #pragma unroll
        for (int ks = 0; ks < 2; ++ks) {
            const int kk = ks * 16;
            wmma::fragment<wmma::matrix_a, 16, 16, 16, __nv_bfloat16, wmma::row_major> af[2];
            wmma::fragment<wmma::matrix_b, 16, 16, 16, __nv_bfloat16, wmma::col_major> bfr[4];
            #pragma unroll
            for (int i = 0; i < 2; ++i)
                wmma::load_matrix_sync(af[i], &As[buf][wm0 + i * 16][kk], 40);
            #pragma unroll
            for (int j = 0; j < 4; ++j)
                wmma::load_matrix_sync(bfr[j], &Bs[buf][wn0 + j * 16][kk], 40);
            #pragma unroll
            for (int i = 0; i < 2; ++i)
                #pragma unroll
                for (int j = 0; j < 4; ++j)
                    wmma::mma_sync(acc[i][j], af[i], bfr[j], acc[i][j]);
        }
        __syncthreads();
    }

    // ---- fused epilogue --------------------------------------------------
    float* stageW = reinterpret_cast<float*>(smraw) + warpI * 320;  // 16x20 per warp
    const int rr = lane >> 1;
    const int cc = (lane & 1) * 8;

    #pragma unroll
    for (int i = 0; i < 2; ++i) {
        #pragma unroll
        for (int j = 0; j < 4; ++j) {
            const int cg0 = bn0 + wn0 + j * 16;
            if (cg0 >= N) continue;          // N % 16 == 0
            wmma::store_matrix_sync(stageW, acc[i][j], 20, wmma::mem_row_major);
            __syncwarp();

            const int gr = bm0 + wm0 + i * 16 + rr;
            const int gc = cg0 + cc;
            float4 v0 = *reinterpret_cast<float4*>(&stageW[rr * 20 + cc]);
            float4 v1 = *reinterpret_cast<float4*>(&stageW[rr * 20 + cc + 4]);
            __syncwarp();                    // frag fully consumed before next store

            if (MODE == 0) {
                const float4 b0 = *reinterpret_cast<const float4*>(&bsum[gc]);
                const float4 b1 = *reinterpret_cast<const float4*>(&bsum[gc + 4]);
                v0.x += b0.x; v0.y += b0.y; v0.z += b0.z; v0.w += b0.w;
                v1.x += b1.x; v1.y += b1.y; v1.z += b1.z; v1.w += b1.w;

                const int bb = gr >> 1, tt = gr & 1;
                #pragma unroll
                for (int q = 0; q < 2; ++q) {
                    float4 v  = q ? v1 : v0;
                    int gcol  = gc + q * 4;
                    int dir   = (gcol >= GATES) ? 1 : 0;
                    int jj    = (gcol - dir * GATES) >> 2;
                    if (tt == dir) {
                        // first step of this direction: c_prev = 0
                        float c = sigm(v.x) * tanhf(v.z);
                        float h = sigm(v.w) * tanhf(c);
                        if (dir == 0) {
                            Cf[bb * HH + jj] = c;
                            Xn[(size_t)bb * 544 + jj] = __float2bfloat16(h);        // hf0
                        } else {
                            Cb[bb * HH + jj] = c;
                            Xn[(size_t)bb * 544 + 408 + jj] = __float2bfloat16(h);  // hb1
                        }
                    } else {
                        *reinterpret_cast<float4*>(&G[(size_t)gr * GCOLS + gcol]) = v;
                    }
                }
            } else {
                const int bb = gr;                       // M == BATCH here
                const size_t grow = (size_t)(2 * bb + 1 - z) * GCOLS + z * GATES;
                float4 q0 = *reinterpret_cast<const float4*>(&G[grow + gc]);
                float4 q1 = *reinterpret_cast<const float4*>(&G[grow + gc + 4]);
                v0.x += q0.x; v0.y += q0.y; v0.z += q0.z; v0.w += q0.w;
                v1.x += q1.x; v1.y += q1.y; v1.z += q1.z; v1.w += q1.w;

                const float* Cp = z ? Cb : Cf;
                const int hoff = z ? 136 : 272;
                #pragma unroll
                for (int q = 0; q < 2; ++q) {
                    float4 v = q ? v1 : v0;
                    int jj   = (gc >> 2) + q;
                    float c  = sigm(v.y) * Cp[bb * HH + jj] + sigm(v.x) * tanhf(v.z);
                    float h  = sigm(v.w) * tanhf(c);
                    Xn[(size_t)bb * 544 + hoff + jj] = __float2bfloat16(h);
                }
            }
        }
    }
}

// ---------------- fused head (reads bf16 activations) -----------------------
#define EPB 2
__global__ __launch_bounds__(128 * EPB)
void head_kernel(const __nv_bfloat16* __restrict__ X,
                 const float* __restrict__ conv_w,
                 const float* __restrict__ conv_b,
                 const float* __restrict__ W_caps,
                 const float* __restrict__ fc1_w,
                 const float* __restrict__ fc1_b,
                 const float* __restrict__ fc2_w,
                 const float* __restrict__ fc2_b,
                 float* __restrict__ out, int out_size)
{
    __shared__ float u[EPB][NCAPS][LL];
    __shared__ float xs[EPB][2][LL];
    __shared__ float scale[EPB][NCAPS];
    __shared__ float uhat[EPB][NCAPS][OUTC];
    __shared__ float vv[EPB][OUTC];
    __shared__ float wred[EPB][4][2];

    const int e = threadIdx.x >> 7;
    const int t = threadIdx.x & 127;
    const int b = blockIdx.x * EPB + e;
    const __nv_bfloat16* x = X + (size_t)b * 544;

    for (int i = t; i < 544; i += 128)
        xs[e][i / LL][i % LL] = __bfloat162float(x[i]);
    __syncthreads();

    for (int idx = t; idx < NCAPS * LL; idx += 128) {
        int c = idx / LL, k = idx % LL;
        int d = (c >> 1) + 1, o = c & 1;
        int left = d >> 1;
        const float* w = conv_w + (size_t)((d - 1) * 2 + o) * 4;
        float acc = conv_b[(d - 1) * 2 + o];
        #pragma unroll
        for (int i = 0; i < 2; ++i)
            #pragma unroll
            for (int kk = 0; kk < 2; ++kk) {
                int p = k + kk * d - left;
                if (p >= 0 && p < LL) acc += w[i * 2 + kk] * xs[e][i][p];
            }
        u[e][c][k] = acc;
    }
    __syncthreads();

    if (t < NCAPS) {
        float s2 = 0.f;
        for (int k = 0; k < LL; ++k) { float q = u[e][t][k]; s2 += q * q; }
        float n = sqrtf(s2);
        scale[e][t] = (1.f - 1.f / (expf(n) + 1e-20f)) / (n + 1e-20f);
    }
    __syncthreads();

    for (int idx = t; idx < NCAPS * OUTC; idx += 128) {
        int c = idx / OUTC, o = idx % OUTC;
        const float* W = W_caps + ((size_t)c * OUTC + o) * LL;
        float acc = 0.f;
        for (int k = 0; k < LL; ++k) acc += W[k] * u[e][c][k];
        uhat[e][c][o] = acc * scale[e][c];
    }
    __syncthreads();

    if (t == 0) {
        float s[OUTC]; float sq = 0.f;
        #pragma unroll
        for (int o = 0; o < OUTC; ++o) {
            float a = 0.f;
            #pragma unroll
            for (int c = 0; c < NCAPS; ++c) a += uhat[e][c][o];
            s[o] = a; sq += a * a;
        }
        float f = sq / (1.f + sq) / sqrtf(sq);
        #pragma unroll
        for (int o = 0; o < OUTC; ++o) vv[e][o] = f * s[o];
    }
    __syncthreads();

    float p0 = 0.f, p1 = 0.f;
    for (int j = t; j < HH; j += 128) {
        float h = fc1_b[j];
        #pragma unroll
        for (int o = 0; o < OUTC; ++o) h += vv[e][o] * fc1_w[j * OUTC + o];
        h = fmaxf(h, 0.f);
        p0 += fc2_w[j] * h;
        p1 += fc2_w[HH + j] * h;
    }
    #pragma unroll
    for (int off = 16; off > 0; off >>= 1) {
        p0 += __shfl_down_sync(0xffffffffu, p0, off);
        p1 += __shfl_down_sync(0xffffffffu, p1, off);
    }
    int lane = t & 31, w = t >> 5;
    if (lane == 0) { wred[e][w][0] = p0; wred[e][w][1] = p1; }
    __syncthreads();

    if (t == 0) {
        float l0 = fc2_b[0], l1 = fc2_b[1];
        #pragma unroll
        for (int ww = 0; ww < 4; ++ww) { l0 += wred[e][ww][0]; l1 += wred[e][ww][1]; }
        out[(size_t)b * 2 + 0] = l0;
        out[(size_t)b * 2 + 1] = l1;
        if (out_size >= 4 * BATCH) {
            float m = fmaxf(l0, l1);
            float e0 = expf(l0 - m), e1 = expf(l1 - m);
            float den = e0 + e1;
            out[(size_t)2 * BATCH + b * 2 + 0] = e0 / den;
            out[(size_t)2 * BATCH + b * 2 + 1] = e1 / den;
        }
    }
}

// ---------------- launch ----------------------------------------------------
extern "C" void kernel_launch(void* const* d_in, const int* in_sizes, int n_in,
                              void* d_out, int out_size)
{
    const int*   seq    = (const int*)  d_in[0];
    const float* sig    = (const float*)d_in[1];
    const float* embed  = (const float*)d_in[2];
    const float* w_ih   = (const float*)d_in[3];
    const float* w_hh   = (const float*)d_in[4];
    const float* b_ih   = (const float*)d_in[5];
    const float* b_hh   = (const float*)d_in[6];
    const float* conv_w = (const float*)d_in[7];
    const float* conv_b = (const float*)d_in[8];
    const float* W_caps = (const float*)d_in[9];
    const float* fc1_w  = (const float*)d_in[10];
    const float* fc1_b  = (const float*)d_in[11];
    const float* fc2_w  = (const float*)d_in[12];
    const float* fc2_b  = (const float*)d_in[13];
    float* out = (float*)d_out;

    __nv_bfloat16 *X0, *X1, *Wih, *Whh;
    float *G, *Cf, *Cb, *Bsum;
    cudaGetSymbolAddress((void**)&X0,   g_Xb0);
    cudaGetSymbolAddress((void**)&X1,   g_Xb1);
    cudaGetSymbolAddress((void**)&G,    g_G);
    cudaGetSymbolAddress((void**)&Cf,   g_Cf);
    cudaGetSymbolAddress((void**)&Cb,   g_Cb);
    cudaGetSymbolAddress((void**)&Wih,  g_Wih);
    cudaGetSymbolAddress((void**)&Whh,  g_Whh);
    cudaGetSymbolAddress((void**)&Bsum, g_Bs);
    __nv_bfloat16* Xs[2] = {X0, X1};

    const int nIH = NL * GCOLS * LL;
    convert_weights<<<(nIH + 255) / 256, 256>>>(w_ih, w_hh, b_ih, b_hh, Wih, Whh, Bsum);
    prep_kernel<<<(BATCH * LL + 255) / 256, 256>>>(seq, sig, embed, X0);

    for (int l = 0; l < NL; ++l) {
        __nv_bfloat16* Xc = Xs[l & 1];
        __nv_bfloat16* Xn = Xs[(l + 1) & 1];

        // input transform + cell1 fused (rows of Xc are (2B,272) contiguous -> lda = LL)
        dim3 g1((GCOLS + 127) / 128, GROWS / 128, 1);
        gemm_fused<0><<<g1, 256>>>(Xc, LL, 0,
                                   Wih + (size_t)l * GCOLS * LL, LL, 0,
                                   G, Bsum + (size_t)l * GCOLS,
                                   Xn, Cf, Cb,
                                   GROWS, GCOLS, LL);

        // recurrent + cell2 fused (both directions via blockIdx.z)
        dim3 g2((GATES + 127) / 128, BATCH / 128, 2);
        gemm_fused<1><<<g2, 256>>>(Xn, 544, 408,
                                   Whh + (size_t)(l * 2) * GATES * HH, HH, (long long)GATES * HH,
                                   G, nullptr,
                                   Xn, Cf, Cb,
                                   BATCH, GATES, HH);
    }

    head_kernel<<<BATCH / EPB, 128 * EPB>>>(X1, conv_w, conv_b, W_caps,
                                            fc1_w, fc1_b, fc2_w, fc2_b,
                                            out, out_size);
}

// round 8
// speedup vs baseline: 2.1547x; 1.1447x over previous
#include <cuda_runtime.h>
#include <cuda_bf16.h>
#include <mma.h>
#include <cstdint>

using namespace nvcuda;

// ---------------- problem constants ----------------
#define BATCH   16384
#define KMER    17
#define HH      136
#define LL      272
#define GATES   544
#define GCOLS   1088
#define NL      3
#define OUTC    16
#define NCAPS   10
#define KCAT    408           // 272 + 136 concatenated K

// ---------------- device scratch --------------------------------------------
__device__ __align__(256) __nv_bfloat16 g_Xb0[(size_t)BATCH * 2 * LL];
__device__ __align__(256) __nv_bfloat16 g_Xb1[(size_t)BATCH * 2 * LL];
__device__ __align__(256) float         g_Cf [(size_t)BATCH * HH];
__device__ __align__(256) float         g_Cb [(size_t)BATCH * HH];
__device__ __align__(256) __nv_bfloat16 g_Wcat[(size_t)NL * 2 * GATES * KCAT];
__device__ __align__(256) float         g_Bs [(size_t)NL * GCOLS];

__device__ __forceinline__ float sigm(float x) { return 1.f / (1.f + expf(-x)); }

__device__ __forceinline__ uint32_t smem_u32(const void* p) {
    uint32_t a;
    asm("{ .reg .u64 t; cvta.to.shared.u64 t, %1; cvt.u32.u64 %0, t; }" : "=r"(a) : "l"(p));
    return a;
}
__device__ __forceinline__ void cp16(uint32_t smaddr, const void* g, int sb) {
    asm volatile("cp.async.cg.shared.global [%0], [%1], 16, %2;\n"
                 :: "r"(smaddr), "l"(g), "r"(sb));
}

// ---------------- weight conversion: gate-permute + K-concat ----------------
// Wcat[(l,d)][n=4j+g][k] = k<272 ? wih[l,d,g*136+j,k] : whh[l,d,g*136+j,k-272]
__global__ void convert_weights(const float* __restrict__ wih,
                                const float* __restrict__ whh,
                                const float* __restrict__ bih,
                                const float* __restrict__ bhh,
                                __nv_bfloat16* __restrict__ wcat,
                                float* __restrict__ bsum)
{
    int i = blockIdx.x * blockDim.x + threadIdx.x;
    const int per = GATES * KCAT;
    const int nW  = NL * 2 * per;
    if (i < nW) {
        int ld = i / per;  int r = i % per;
        int n = r / KCAT, k = r % KCAT;
        int j = n >> 2, g = n & 3;
        float v = (k < 272)
            ? wih[((size_t)ld * GATES + g * HH + j) * LL + k]
            : whh[((size_t)ld * GATES + g * HH + j) * HH + (k - 272)];
        wcat[i] = __float2bfloat16(v);
    }
    if (i < NL * GCOLS) {
        int l = i / GCOLS; int np = i % GCOLS;
        int d = np / GATES, q = np % GATES;
        int j = q >> 2, g = q & 3;
        int src = (l * 2 + d) * GATES + g * HH + j;
        bsum[i] = bih[src] + bhh[src];
    }
}

// ---------------- prep: build layer-0 input (bf16) --------------------------
__global__ void prep_kernel(const int* __restrict__ seq,
                            const float* __restrict__ sig,
                            const float* __restrict__ embed,
                            __nv_bfloat16* __restrict__ X)
{
    int idx = blockIdx.x * blockDim.x + threadIdx.x;
    if (idx >= BATCH * LL) return;
    int b = idx / LL, r = idx % LL;
    int p = r >> 4, e = r & 15;
    int tok = seq[b * KMER + p];
    X[(size_t)b * 544 + r]       = __float2bfloat16(embed[tok * 16 + e]);
    X[(size_t)b * 544 + 272 + r] = __float2bfloat16(sig[(size_t)b * LL + r]);
}

// ---------------- fused LSTM GEMM (wmma bf16, NT) ----------------------------
// Block tile 128x128, BK=64, double-buffered cp.async, 8 warps (32x64 each).
// z = blockIdx.z = direction.
// MODE 0: gates_first = x_first @ Wih^T + b ; cell1 (c_prev=0) -> h, C.
// MODE 1: gates_second = [x_second | h_first] @ Wcat^T + b ; cell2 -> h.
template<int KACT, int MODE>
__global__ __launch_bounds__(256)
void gemm_lstm(const __nv_bfloat16* __restrict__ Xc,
               const __nv_bfloat16* __restrict__ Wcat,   // layer base
               const float* __restrict__ bsum,           // layer base (1088)
               __nv_bfloat16* __restrict__ Xn,
               float* __restrict__ Cf, float* __restrict__ Cb)
{
    extern __shared__ __align__(16) char dsm[];
    // layout (bf16, row stride 72): A[2][128][72] @0, B[2][128][72] @36864
    const int STG = 128 * 72 * 2;          // 18432 bytes per stage per matrix

    const int tid   = threadIdx.x;
    const int warpI = tid >> 5;
    const int lane  = tid & 31;
    const int z     = blockIdx.z;
    const int bm0   = blockIdx.y * 128;
    const int bn0   = blockIdx.x * 128;
    const int wm0   = (warpI & 3) * 32;
    const int wn0   = (warpI >> 2) * 64;

    const uint32_t smA = smem_u32(dsm);
    const uint32_t smB = smA + 2 * STG;

    const __nv_bfloat16* A1 = Xc + (MODE == 0 ? z * 272 : (1 - z) * 272);
    const __nv_bfloat16* A2 = Xn + z * 408;                  // h_first slots
    const __nv_bfloat16* Bsrc = Wcat + (size_t)z * GATES * KCAT;

    wmma::fragment<wmma::accumulator, 16, 16, 16, float> acc[2][4];
    #pragma unroll
    for (int i = 0; i < 2; ++i)
        #pragma unroll
        for (int j = 0; j < 4; ++j)
            wmma::fill_fragment(acc[i][j], 0.0f);

    const int nS = (KACT + 63) >> 6;

    auto load_stage = [&](int s, int buf) {
        const int k0 = s * 64;
        #pragma unroll
        for (int it = 0; it < 4; ++it) {
            int c   = tid + it * 256;          // 0..1023
            int row = c >> 3;
            int kc  = (c & 7) * 8;
            int kg  = k0 + kc;
            bool kv = kg < KACT;
            // A
            const __nv_bfloat16* ap;
            if (MODE == 0 || kg < 272)
                ap = A1 + (size_t)(bm0 + row) * 544 + (kv ? kg : 0);
            else
                ap = A2 + (size_t)(bm0 + row) * 544 + (kv ? (kg - 272) : 0);
            cp16(smA + buf * STG + row * 144 + kc * 2, ap, kv ? 16 : 0);
            // B
            int n   = bn0 + row;
            bool bok = kv && (n < GATES);
            const __nv_bfloat16* bp = Bsrc + (size_t)(n < GATES ? n : 0) * KCAT
                                           + (kv ? kg : 0);
            cp16(smB + buf * STG + row * 144 + kc * 2, bp, bok ? 16 : 0);
        }
        asm volatile("cp.async.commit_group;\n");
    };

    load_stage(0, 0);

    for (int s = 0; s < nS; ++s) {
        const int buf = s & 1;
        if (s + 1 < nS) {
            load_stage(s + 1, buf ^ 1);
            asm volatile("cp.async.wait_group 1;\n");
        } else {
            asm volatile("cp.async.wait_group 0;\n");
        }
        __syncthreads();

        const __nv_bfloat16* Ab = reinterpret_cast<const __nv_bfloat16*>(dsm) + buf * (128 * 72);
        const __nv_bfloat16* Bb = reinterpret_cast<const __nv_bfloat16*>(dsm + 2 * STG) + buf * (128 * 72);

        #pragma unroll
        for (int ks = 0; ks < 4; ++ks) {
            const int kk = ks * 16;
            wmma::fragment<wmma::matrix_a, 16, 16, 16, __nv_bfloat16, wmma::row_major> af[2];
            wmma::fragment<wmma::matrix_b, 16, 16, 16, __nv_bfloat16, wmma::col_major> bfr[4];
            #pragma unroll
            for (int i = 0; i < 2; ++i)
                wmma::load_matrix_sync(af[i], Ab + (wm0 + i * 16) * 72 + kk, 72);
            #pragma unroll
            for (int j = 0; j < 4; ++j)
                wmma::load_matrix_sync(bfr[j], Bb + (wn0 + j * 16) * 72 + kk, 72);
            #pragma unroll
            for (int i = 0; i < 2; ++i)
                #pragma unroll
                for (int j = 0; j < 4; ++j)
                    wmma::mma_sync(acc[i][j], af[i], bfr[j], acc[i][j]);
        }
        __syncthreads();
    }

    // ---- fused LSTM epilogue ----------------------------------------------
    float* stageW = reinterpret_cast<float*>(dsm) + warpI * 320;  // 16x20 per warp
    const int rr = lane >> 1;
    const int cc = (lane & 1) * 8;

    const float* bs = bsum + z * 544;
    float* Csel = z ? Cb : Cf;
    const int hoff = (MODE == 0) ? (z ? 408 : 0) : (z ? 136 : 272);

    #pragma unroll
    for (int i = 0; i < 2; ++i) {
        #pragma unroll
        for (int j = 0; j < 4; ++j) {
            const int cg0 = bn0 + wn0 + j * 16;
            if (cg0 >= GATES) continue;       // GATES % 16 == 0
            wmma::store_matrix_sync(stageW, acc[i][j], 20, wmma::mem_row_major);
            __syncwarp();

            const int b  = bm0 + wm0 + i * 16 + rr;     // batch index
            const int gc = cg0 + cc;
            float4 v0 = *reinterpret_cast<float4*>(&stageW[rr * 20 + cc]);
            float4 v1 = *reinterpret_cast<float4*>(&stageW[rr * 20 + cc + 4]);
            __syncwarp();

            const float4 b0 = *reinterpret_cast<const float4*>(bs + gc);
            const float4 b1 = *reinterpret_cast<const float4*>(bs + gc + 4);

            #pragma unroll
            for (int q = 0; q < 2; ++q) {
                float4 v  = q ? v1 : v0;
                float4 bb = q ? b1 : b0;
                int j2 = ((gc + q * 4) >> 2);             // hidden unit index
                float gi = v.x + bb.x;
                float gf = v.y + bb.y;
                float gg = v.z + bb.z;
                float go = v.w + bb.w;
                float c;
                if (MODE == 0) c = sigm(gi) * tanhf(gg);
                else           c = sigm(gf) * Csel[(size_t)b * HH + j2]
                                 + sigm(gi) * tanhf(gg);
                float h = sigm(go) * tanhf(c);
                if (MODE == 0) Csel[(size_t)b * HH + j2] = c;
                Xn[(size_t)b * 544 + hoff + j2] = __float2bfloat16(h);
            }
        }
    }
}

// ---------------- fused head (EPB=4, dynamic smem) ---------------------------
#define EPB 4
__global__ __launch_bounds__(128 * EPB)
void head_kernel(const __nv_bfloat16* __restrict__ X,
                 const float* __restrict__ conv_w,
                 const float* __restrict__ conv_b,
                 const float* __restrict__ W_caps,
                 const float* __restrict__ fc1_w,
                 const float* __restrict__ fc1_b,
                 const float* __restrict__ fc2_w,
                 const float* __restrict__ fc2_b,
                 float* __restrict__ out, int out_size)
{
    extern __shared__ float hsm[];
    // carve
    float* xs_a    = hsm;                         // EPB*2*LL   = 2176
    float* u_a     = xs_a + EPB * 2 * LL;         // EPB*10*LL  = 10880
    float* scale_a = u_a + EPB * NCAPS * LL;      // EPB*10
    float* uhat_a  = scale_a + EPB * NCAPS;       // EPB*160
    float* vv_a    = uhat_a + EPB * NCAPS * OUTC; // EPB*16
    float* wred_a  = vv_a + EPB * OUTC;           // EPB*8

    const int e = threadIdx.x >> 7;
    const int t = threadIdx.x & 127;
    const int b = blockIdx.x * EPB + e;
    const __nv_bfloat16* x = X + (size_t)b * 544;

    float* xs    = xs_a    + e * 2 * LL;
    float* u     = u_a     + e * NCAPS * LL;
    float* scale = scale_a + e * NCAPS;
    float* uhat  = uhat_a  + e * NCAPS * OUTC;
    float* vv    = vv_a    + e * OUTC;
    float* wred  = wred_a  + e * 8;

    for (int i = t; i < 544; i += 128)
        xs[i] = __bfloat162float(x[i]);
    __syncthreads();

    for (int idx = t; idx < NCAPS * LL; idx += 128) {
        int c = idx / LL, k = idx % LL;
        int dd = (c >> 1) + 1, o = c & 1;
        int left = dd >> 1;
        const float* w = conv_w + (size_t)((dd - 1) * 2 + o) * 4;
        float acc = conv_b[(dd - 1) * 2 + o];
        #pragma unroll
        for (int i = 0; i < 2; ++i)
            #pragma unroll
            for (int kk = 0; kk < 2; ++kk) {
                int p = k + kk * dd - left;
                if (p >= 0 && p < LL) acc += w[i * 2 + kk] * xs[i * LL + p];
            }
        u[c * LL + k] = acc;
    }
    __syncthreads();

    if (t < NCAPS) {
        float s2 = 0.f;
        for (int k = 0; k < LL; ++k) { float q = u[t * LL + k]; s2 += q * q; }
        float n = sqrtf(s2);
        scale[t] = (1.f - 1.f / (expf(n) + 1e-20f)) / (n + 1e-20f);
    }
    __syncthreads();

    for (int idx = t; idx < NCAPS * OUTC; idx += 128) {
        int c = idx / OUTC, o = idx % OUTC;
        const float* W = W_caps + ((size_t)c * OUTC + o) * LL;
        float acc = 0.f;
        for (int k = 0; k < LL; ++k) acc += W[k] * u[c * LL + k];
        uhat[c * OUTC + o] = acc * scale[c];
    }
    __syncthreads();

    if (t == 0) {
        float s[OUTC]; float sq = 0.f;
        #pragma unroll
        for (int o = 0; o < OUTC; ++o) {
            float a = 0.f;
            #pragma unroll
            for (int c = 0; c < NCAPS; ++c) a += uhat[c * OUTC + o];
            s[o] = a; sq += a * a;
        }
        float f = sq / (1.f + sq) / sqrtf(sq);
        #pragma unroll
        for (int o = 0; o < OUTC; ++o) vv[o] = f * s[o];
    }
    __syncthreads();

    float p0 = 0.f, p1 = 0.f;
    for (int j = t; j < HH; j += 128) {
        float h = fc1_b[j];
        #pragma unroll
        for (int o = 0; o < OUTC; ++o) h += vv[o] * fc1_w[j * OUTC + o];
        h = fmaxf(h, 0.f);
        p0 += fc2_w[j] * h;
        p1 += fc2_w[HH + j] * h;
    }
    #pragma unroll
    for (int off = 16; off > 0; off >>= 1) {
        p0 += __shfl_down_sync(0xffffffffu, p0, off);
        p1 += __shfl_down_sync(0xffffffffu, p1, off);
    }
    int lane = t & 31, w = t >> 5;
    if (lane == 0) { wred[w * 2 + 0] = p0; wred[w * 2 + 1] = p1; }
    __syncthreads();

    if (t == 0) {
        float l0 = fc2_b[0], l1 = fc2_b[1];
        #pragma unroll
        for (int ww = 0; ww < 4; ++ww) { l0 += wred[ww * 2 + 0]; l1 += wred[ww * 2 + 1]; }
        out[(size_t)b * 2 + 0] = l0;
        out[(size_t)b * 2 + 1] = l1;
        if (out_size >= 4 * BATCH) {
            float m = fmaxf(l0, l1);
            float e0 = expf(l0 - m), e1 = expf(l1 - m);
            float den = e0 + e1;
            out[(size_t)2 * BATCH + b * 2 + 0] = e0 / den;
            out[(size_t)2 * BATCH + b * 2 + 1] = e1 / den;
        }
    }
}

// ---------------- launch ----------------------------------------------------
extern "C" void kernel_launch(void* const* d_in, const int* in_sizes, int n_in,
                              void* d_out, int out_size)
{
    const int*   seq    = (const int*)  d_in[0];
    const float* sig    = (const float*)d_in[1];
    const float* embed  = (const float*)d_in[2];
    const float* w_ih   = (const float*)d_in[3];
    const float* w_hh   = (const float*)d_in[4];
    const float* b_ih   = (const float*)d_in[5];
    const float* b_hh   = (const float*)d_in[6];
    const float* conv_w = (const float*)d_in[7];
    const float* conv_b = (const float*)d_in[8];
    const float* W_caps = (const float*)d_in[9];
    const float* fc1_w  = (const float*)d_in[10];
    const float* fc1_b  = (const float*)d_in[11];
    const float* fc2_w  = (const float*)d_in[12];
    const float* fc2_b  = (const float*)d_in[13];
    float* out = (float*)d_out;

    __nv_bfloat16 *X0, *X1, *Wcat;
    float *Cf, *Cb, *Bsum;
    cudaGetSymbolAddress((void**)&X0,   g_Xb0);
    cudaGetSymbolAddress((void**)&X1,   g_Xb1);
    cudaGetSymbolAddress((void**)&Cf,   g_Cf);
    cudaGetSymbolAddress((void**)&Cb,   g_Cb);
    cudaGetSymbolAddress((void**)&Wcat, g_Wcat);
    cudaGetSymbolAddress((void**)&Bsum, g_Bs);
    __nv_bfloat16* Xs[2] = {X0, X1};

    const int SMEM_G = 4 * 128 * 72 * 2;         // 73728
    const int SMEM_H = (EPB * (2*LL + NCAPS*LL + NCAPS + NCAPS*OUTC + OUTC + 8)) * 4;
    cudaFuncSetAttribute(gemm_lstm<272, 0>,
                         cudaFuncAttributeMaxDynamicSharedMemorySize, SMEM_G);
    cudaFuncSetAttribute(gemm_lstm<408, 1>,
                         cudaFuncAttributeMaxDynamicSharedMemorySize, SMEM_G);
    cudaFuncSetAttribute(head_kernel,
                         cudaFuncAttributeMaxDynamicSharedMemorySize, SMEM_H);

    const int nW = NL * 2 * GATES * KCAT;
    convert_weights<<<(nW + 255) / 256, 256>>>(w_ih, w_hh, b_ih, b_hh, Wcat, Bsum);
    prep_kernel<<<(BATCH * LL + 255) / 256, 256>>>(seq, sig, embed, X0);

    dim3 grid(5, BATCH / 128, 2);
    for (int l = 0; l < NL; ++l) {
        __nv_bfloat16* Xc = Xs[l & 1];
        __nv_bfloat16* Xn = Xs[(l + 1) & 1];
        const __nv_bfloat16* Wl = Wcat + (size_t)l * 2 * GATES * KCAT;
        const float* Bl = Bsum + (size_t)l * GCOLS;

        gemm_lstm<272, 0><<<grid, 256, SMEM_G>>>(Xc, Wl, Bl, Xn, Cf, Cb);
        gemm_lstm<408, 1><<<grid, 256, SMEM_G>>>(Xc, Wl, Bl, Xn, Cf, Cb);
    }

    head_kernel<<<BATCH / EPB, 128 * EPB, SMEM_H>>>(X1, conv_w, conv_b, W_caps,
                                                    fc1_w, fc1_b, fc2_w, fc2_b,
                                                    out, out_size);
}

// round 9
// speedup vs baseline: 4.8402x; 2.2463x over previous
#include <cuda_runtime.h>
#include <cuda_bf16.h>
#include <mma.h>
#include <cstdint>

using namespace nvcuda;

// ---------------- problem constants ----------------
#define BATCH   16384
#define KMER    17
#define HH      136
#define LL      272
#define GATES   544
#define GCOLS   1088
#define NL      3
#define OUTC    16
#define NCAPS   10
#define KCAT    408           // 272 + 136 concatenated K

// ---------------- device scratch --------------------------------------------
__device__ __align__(256) __nv_bfloat16 g_Xb0[(size_t)BATCH * 2 * LL];
__device__ __align__(256) __nv_bfloat16 g_Xb1[(size_t)BATCH * 2 * LL];
__device__ __align__(256) float         g_Cf [(size_t)BATCH * HH];
__device__ __align__(256) float         g_Cb [(size_t)BATCH * HH];
__device__ __align__(256) __nv_bfloat16 g_Wcat[(size_t)NL * 2 * GATES * KCAT];
__device__ __align__(256) float         g_Bs [(size_t)NL * GCOLS];
__device__ __align__(256) __nv_bfloat16 g_Wcb[(size_t)NCAPS * OUTC * LL];   // W_caps bf16

__device__ __forceinline__ float sigm(float x) { return 1.f / (1.f + expf(-x)); }

__device__ __forceinline__ uint32_t smem_u32(const void* p) {
    uint32_t a;
    asm("{ .reg .u64 t; cvta.to.shared.u64 t, %1; cvt.u32.u64 %0, t; }" : "=r"(a) : "l"(p));
    return a;
}
__device__ __forceinline__ void cp16(uint32_t smaddr, const void* g, int sb) {
    asm volatile("cp.async.cg.shared.global [%0], [%1], 16, %2;\n"
                 :: "r"(smaddr), "l"(g), "r"(sb));
}
__device__ __forceinline__ void cp_wait_n(int n) {
    if (n <= 0)      asm volatile("cp.async.wait_group 0;");
    else if (n == 1) asm volatile("cp.async.wait_group 1;");
    else             asm volatile("cp.async.wait_group 2;");
}

// ---------------- setup: prep input + all weight conversions (1 launch) -----
__global__ void setup_kernel(const int* __restrict__ seq,
                             const float* __restrict__ sig,
                             const float* __restrict__ embed,
                             const float* __restrict__ wih,
                             const float* __restrict__ whh,
                             const float* __restrict__ bih,
                             const float* __restrict__ bhh,
                             const float* __restrict__ wcaps,
                             __nv_bfloat16* __restrict__ X,
                             __nv_bfloat16* __restrict__ wcat,
                             float* __restrict__ bsum,
                             __nv_bfloat16* __restrict__ wcb)
{
    const long long nPrep = (long long)BATCH * LL;                 // 4456448
    const long long nW    = (long long)NL * 2 * GATES * KCAT;      // 1331712
    const long long nB    = NL * GCOLS;                            // 3264
    const long long nC    = NCAPS * OUTC * LL;                     // 43520
    long long i = (long long)blockIdx.x * blockDim.x + threadIdx.x;

    if (i < nPrep) {
        int b = (int)(i / LL), r = (int)(i % LL);
        int p = r >> 4, e = r & 15;
        int tok = seq[b * KMER + p];
        X[(size_t)b * 544 + r]       = __float2bfloat16(embed[tok * 16 + e]);
        X[(size_t)b * 544 + 272 + r] = __float2bfloat16(sig[(size_t)b * LL + r]);
        return;
    }
    i -= nPrep;
    if (i < nW) {
        const int per = GATES * KCAT;
        int ld = (int)(i / per);  int r = (int)(i % per);
        int n = r / KCAT, k = r % KCAT;
        int j = n >> 2, g = n & 3;
        float v = (k < 272)
            ? wih[((size_t)ld * GATES + g * HH + j) * LL + k]
            : whh[((size_t)ld * GATES + g * HH + j) * HH + (k - 272)];
        wcat[i] = __float2bfloat16(v);
        return;
    }
    i -= nW;
    if (i < nB) {
        int l = (int)(i / GCOLS); int np = (int)(i % GCOLS);
        int d = np / GATES, q = np % GATES;
        int j = q >> 2, g = q & 3;
        int src = (l * 2 + d) * GATES + g * HH + j;
        bsum[i] = bih[src] + bhh[src];
        return;
    }
    i -= nB;
    if (i < nC) wcb[i] = __float2bfloat16(wcaps[i]);
}

// ---------------- fused LSTM GEMM (wmma bf16, NT, 3-stage pipeline) ----------
// Block tile 128x128, BK=64, 8 warps (32x64 each). z = blockIdx.z = direction.
// MODE 0: gates_first = x_first @ Wih^T + b ; cell1 (c_prev=0) -> h, C.
// MODE 1: gates_second = [x_second | h_first] @ Wcat^T + b ; cell2 -> h.
template<int KACT, int MODE>
__global__ __launch_bounds__(256)
void gemm_lstm(const __nv_bfloat16* __restrict__ Xc,
               const __nv_bfloat16* __restrict__ Wcat,   // layer base
               const float* __restrict__ bsum,           // layer base (1088)
               __nv_bfloat16* __restrict__ Xn,
               float* __restrict__ Cf, float* __restrict__ Cb)
{
    extern __shared__ __align__(16) char dsm[];
    const int STG = 128 * 72 * 2;          // 18432 bytes per stage per matrix
    // layout: A[3][128][72] @0 ; B[3][128][72] @ 3*STG

    const int tid   = threadIdx.x;
    const int warpI = tid >> 5;
    const int lane  = tid & 31;
    const int z     = blockIdx.z;
    const int bm0   = blockIdx.y * 128;
    const int bn0   = blockIdx.x * 128;
    const int wm0   = (warpI & 3) * 32;
    const int wn0   = (warpI >> 2) * 64;

    const uint32_t smA = smem_u32(dsm);
    const uint32_t smB = smA + 3 * STG;

    const __nv_bfloat16* A1 = Xc + (MODE == 0 ? z * 272 : (1 - z) * 272);
    const __nv_bfloat16* A2 = Xn + z * 408;                  // h_first slots
    const __nv_bfloat16* Bsrc = Wcat + (size_t)z * GATES * KCAT;

    wmma::fragment<wmma::accumulator, 16, 16, 16, float> acc[2][4];
    #pragma unroll
    for (int i = 0; i < 2; ++i)
        #pragma unroll
        for (int j = 0; j < 4; ++j)
            wmma::fill_fragment(acc[i][j], 0.0f);

    const int nS = (KACT + 63) >> 6;

    auto load_stage = [&](int s, int buf) {
        const int k0 = s * 64;
        #pragma unroll
        for (int it = 0; it < 4; ++it) {
            int c   = tid + it * 256;          // 0..1023
            int row = c >> 3;
            int kc  = (c & 7) * 8;
            int kg  = k0 + kc;
            bool kv = kg < KACT;
            const __nv_bfloat16* ap;
            if (MODE == 0 || kg < 272)
                ap = A1 + (size_t)(bm0 + row) * 544 + (kv ? kg : 0);
            else
                ap = A2 + (size_t)(bm0 + row) * 544 + (kv ? (kg - 272) : 0);
            cp16(smA + buf * STG + row * 144 + kc * 2, ap, kv ? 16 : 0);
            int n   = bn0 + row;
            bool bok = kv && (n < GATES);
            const __nv_bfloat16* bp = Bsrc + (size_t)(n < GATES ? n : 0) * KCAT
                                           + (kv ? kg : 0);
            cp16(smB + buf * STG + row * 144 + kc * 2, bp, bok ? 16 : 0);
        }
        asm volatile("cp.async.commit_group;\n");
    };

    load_stage(0, 0);
    if (nS > 1) load_stage(1, 1);

    for (int s = 0; s < nS; ++s) {
        if (s + 2 < nS) load_stage(s + 2, (s + 2) % 3);
        cp_wait_n(nS - 1 - s < 2 ? nS - 1 - s : 2);
        __syncthreads();

        const int buf = s % 3;
        const __nv_bfloat16* Ab = reinterpret_cast<const __nv_bfloat16*>(dsm) + buf * (128 * 72);
        const __nv_bfloat16* Bb = reinterpret_cast<const __nv_bfloat16*>(dsm + 3 * STG) + buf * (128 * 72);

        #pragma unroll
        for (int ks = 0; ks < 4; ++ks) {
            const int kk = ks * 16;
            wmma::fragment<wmma::matrix_a, 16, 16, 16, __nv_bfloat16, wmma::row_major> af[2];
            wmma::fragment<wmma::matrix_b, 16, 16, 16, __nv_bfloat16, wmma::col_major> bfr[4];
            #pragma unroll
            for (int i = 0; i < 2; ++i)
                wmma::load_matrix_sync(af[i], Ab + (wm0 + i * 16) * 72 + kk, 72);
            #pragma unroll
            for (int j = 0; j < 4; ++j)
                wmma::load_matrix_sync(bfr[j], Bb + (wn0 + j * 16) * 72 + kk, 72);
            #pragma unroll
            for (int i = 0; i < 2; ++i)
                #pragma unroll
                for (int j = 0; j < 4; ++j)
                    wmma::mma_sync(acc[i][j], af[i], bfr[j], acc[i][j]);
        }
        __syncthreads();
    }

    // ---- fused LSTM epilogue ----------------------------------------------
    float* stageW = reinterpret_cast<float*>(dsm) + warpI * 320;  // 16x20 per warp
    const int rr = lane >> 1;
    const int cc = (lane & 1) * 8;

    const float* bs = bsum + z * 544;
    float* Csel = z ? Cb : Cf;
    const int hoff = (MODE == 0) ? (z ? 408 : 0) : (z ? 136 : 272);

    #pragma unroll
    for (int i = 0; i < 2; ++i) {
        #pragma unroll
        for (int j = 0; j < 4; ++j) {
            const int cg0 = bn0 + wn0 + j * 16;
            if (cg0 >= GATES) continue;
            wmma::store_matrix_sync(stageW, acc[i][j], 20, wmma::mem_row_major);
            __syncwarp();

            const int b  = bm0 + wm0 + i * 16 + rr;
            const int gc = cg0 + cc;
            float4 v0 = *reinterpret_cast<float4*>(&stageW[rr * 20 + cc]);
            float4 v1 = *reinterpret_cast<float4*>(&stageW[rr * 20 + cc + 4]);
            __syncwarp();

            const float4 b0 = *reinterpret_cast<const float4*>(bs + gc);
            const float4 b1 = *reinterpret_cast<const float4*>(bs + gc + 4);

            #pragma unroll
            for (int q = 0; q < 2; ++q) {
                float4 v  = q ? v1 : v0;
                float4 bb = q ? b1 : b0;
                int j2 = ((gc + q * 4) >> 2);
                float gi = v.x + bb.x;
                float gf = v.y + bb.y;
                float gg = v.z + bb.z;
                float go = v.w + bb.w;
                float c;
                if (MODE == 0) c = sigm(gi) * tanhf(gg);
                else           c = sigm(gf) * Csel[(size_t)b * HH + j2]
                                 + sigm(gi) * tanhf(gg);
                float h = sigm(go) * tanhf(c);
                if (MODE == 0) Csel[(size_t)b * HH + j2] = c;
                Xn[(size_t)b * 544 + hoff + j2] = __float2bfloat16(h);
            }
        }
    }
}

// ---------------- fused head: cooperative, W shared across 4 elements -------
#define EPB 4
__global__ __launch_bounds__(128 * EPB)
void head_kernel(const __nv_bfloat16* __restrict__ X,
                 const float* __restrict__ conv_w,
                 const float* __restrict__ conv_b,
                 const __nv_bfloat16* __restrict__ Wcb,   // bf16 W_caps (10,16,272)
                 const float* __restrict__ fc1_w,
                 const float* __restrict__ fc1_b,
                 const float* __restrict__ fc2_w,
                 const float* __restrict__ fc2_b,
                 float* __restrict__ out, int out_size)
{
    extern __shared__ float hsm[];
    float* xs_a    = hsm;                          // 4*544  = 2176
    float* u_a     = xs_a + EPB * 2 * LL;          // 4*2720 = 10880
    float* sred_a  = u_a + EPB * NCAPS * LL;       // 4*10*4 = 160
    float* scale_a = sred_a + EPB * NCAPS * 4;     // 4*10
    float* uhat_a  = scale_a + EPB * NCAPS;        // 4*160
    float* vv_a    = uhat_a + EPB * NCAPS * OUTC;  // 4*16
    float* wred_a  = vv_a + EPB * OUTC;            // 4*8

    const int tid  = threadIdx.x;
    const int e    = tid >> 7;
    const int t    = tid & 127;
    const int lane = tid & 31;
    const int W16  = tid >> 5;          // 0..15 block warp
    const int w4   = W16 & 3;           // warp within element group
    const int b    = blockIdx.x * EPB + e;
    const __nv_bfloat16* x = X + (size_t)b * 544;

    float* xs    = xs_a    + e * 2 * LL;
    float* u     = u_a     + e * NCAPS * LL;
    float* scale = scale_a + e * NCAPS;
    float* vv    = vv_a    + e * OUTC;
    float* wred  = wred_a  + e * 8;

    // ---- stage x ----
    for (int i = t; i < 544; i += 128)
        xs[i] = __bfloat162float(x[i]);
    __syncthreads();

    // ---- dilated convs ----
    for (int idx = t; idx < NCAPS * LL; idx += 128) {
        int c = idx / LL, k = idx % LL;
        int dd = (c >> 1) + 1, o = c & 1;
        int left = dd >> 1;
        const float* w = conv_w + (size_t)((dd - 1) * 2 + o) * 4;
        float acc = conv_b[(dd - 1) * 2 + o];
        #pragma unroll
        for (int i = 0; i < 2; ++i)
            #pragma unroll
            for (int kk = 0; kk < 2; ++kk) {
                int p = k + kk * dd - left;
                if (p >= 0 && p < LL) acc += w[i * 2 + kk] * xs[i * LL + p];
            }
        u[c * LL + k] = acc;
    }
    __syncthreads();

    // ---- per-capsule norms (parallel reduce; 128 threads per element) ----
    #pragma unroll
    for (int c = 0; c < NCAPS; ++c) {
        float q0 = u[c * LL + t];
        float q1 = u[c * LL + t + 128];
        float p  = q0 * q0 + q1 * q1;
        if (t < 16) { float q2 = u[c * LL + t + 256]; p += q2 * q2; }
        #pragma unroll
        for (int off = 16; off > 0; off >>= 1)
            p += __shfl_down_sync(0xffffffffu, p, off);
        if (lane == 0) sred_a[(e * NCAPS + c) * 4 + w4] = p;
    }
    __syncthreads();
    if (t < NCAPS) {
        const float* sr = &sred_a[(e * NCAPS + t) * 4];
        float s2 = sr[0] + sr[1] + sr[2] + sr[3];
        float n = sqrtf(s2);
        scale[t] = (1.f - 1.f / (expf(n) + 1e-20f)) / (n + 1e-20f);
    }
    __syncthreads();

    // ---- u_hat: block-cooperative, W row shared across 4 elements ----
    for (int p = W16; p < NCAPS * OUTC; p += 16) {
        int c = p >> 4;
        const __nv_bfloat16* wr = Wcb + (size_t)p * LL;
        float a0 = 0.f, a1 = 0.f, a2 = 0.f, a3 = 0.f;
        #pragma unroll
        for (int s = 0; s < 9; ++s) {
            int k = s * 32 + lane;
            if (k < LL) {
                float wv = __bfloat162float(wr[k]);
                a0 += wv * u_a[0 * NCAPS * LL + c * LL + k];
                a1 += wv * u_a[1 * NCAPS * LL + c * LL + k];
                a2 += wv * u_a[2 * NCAPS * LL + c * LL + k];
                a3 += wv * u_a[3 * NCAPS * LL + c * LL + k];
            }
        }
        #pragma unroll
        for (int off = 16; off > 0; off >>= 1) {
            a0 += __shfl_down_sync(0xffffffffu, a0, off);
            a1 += __shfl_down_sync(0xffffffffu, a1, off);
            a2 += __shfl_down_sync(0xffffffffu, a2, off);
            a3 += __shfl_down_sync(0xffffffffu, a3, off);
        }
        if (lane == 0) {
            uhat_a[0 * 160 + p] = a0 * scale_a[0 * NCAPS + c];
            uhat_a[1 * 160 + p] = a1 * scale_a[1 * NCAPS + c];
            uhat_a[2 * 160 + p] = a2 * scale_a[2 * NCAPS + c];
            uhat_a[3 * 160 + p] = a3 * scale_a[3 * NCAPS + c];
        }
    }
    __syncthreads();

    // ---- v = squash(sum_c u_hat): lanes 0..15 of each group's warp 0 ----
    if (t < OUTC) {
        float s = 0.f;
        #pragma unroll
        for (int c = 0; c < NCAPS; ++c) s += uhat_a[e * 160 + c * OUTC + t];
        float sq = s * s;
        #pragma unroll
        for (int off = 8; off > 0; off >>= 1)
            sq += __shfl_xor_sync(0x0000ffffu, sq, off);
        float f = sq / (1.f + sq) / sqrtf(sq);
        vv[t] = f * s;
    }
    __syncthreads();

    // ---- fc1 (relu) + fc2 ----
    float p0 = 0.f, p1 = 0.f;
    for (int j = t; j < HH; j += 128) {
        float h = fc1_b[j];
        #pragma unroll
        for (int o = 0; o < OUTC; ++o) h += vv[o] * fc1_w[j * OUTC + o];
        h = fmaxf(h, 0.f);
        p0 += fc2_w[j] * h;
        p1 += fc2_w[HH + j] * h;
    }
    #pragma unroll
    for (int off = 16; off > 0; off >>= 1) {
        p0 += __shfl_down_sync(0xffffffffu, p0, off);
        p1 += __shfl_down_sync(0xffffffffu, p1, off);
    }
    if (lane == 0) { wred[w4 * 2 + 0] = p0; wred[w4 * 2 + 1] = p1; }
    __syncthreads();

    if (t == 0) {
        float l0 = fc2_b[0], l1 = fc2_b[1];
        #pragma unroll
        for (int ww = 0; ww < 4; ++ww) { l0 += wred[ww * 2 + 0]; l1 += wred[ww * 2 + 1]; }
        out[(size_t)b * 2 + 0] = l0;
        out[(size_t)b * 2 + 1] = l1;
        if (out_size >= 4 * BATCH) {
            float m = fmaxf(l0, l1);
            float e0 = expf(l0 - m), e1 = expf(l1 - m);
            float den = e0 + e1;
            out[(size_t)2 * BATCH + b * 2 + 0] = e0 / den;
            out[(size_t)2 * BATCH + b * 2 + 1] = e1 / den;
        }
    }
}

// ---------------- launch ----------------------------------------------------
extern "C" void kernel_launch(void* const* d_in, const int* in_sizes, int n_in,
                              void* d_out, int out_size)
{
    const int*   seq    = (const int*)  d_in[0];
    const float* sig    = (const float*)d_in[1];
    const float* embed  = (const float*)d_in[2];
    const float* w_ih   = (const float*)d_in[3];
    const float* w_hh   = (const float*)d_in[4];
    const float* b_ih   = (const float*)d_in[5];
    const float* b_hh   = (const float*)d_in[6];
    const float* conv_w = (const float*)d_in[7];
    const float* conv_b = (const float*)d_in[8];
    const float* W_caps = (const float*)d_in[9];
    const float* fc1_w  = (const float*)d_in[10];
    const float* fc1_b  = (const float*)d_in[11];
    const float* fc2_w  = (const float*)d_in[12];
    const float* fc2_b  = (const float*)d_in[13];
    float* out = (float*)d_out;

    __nv_bfloat16 *X0, *X1, *Wcat, *Wcb;
    float *Cf, *Cb, *Bsum;
    cudaGetSymbolAddress((void**)&X0,   g_Xb0);
    cudaGetSymbolAddress((void**)&X1,   g_Xb1);
    cudaGetSymbolAddress((void**)&Cf,   g_Cf);
    cudaGetSymbolAddress((void**)&Cb,   g_Cb);
    cudaGetSymbolAddress((void**)&Wcat, g_Wcat);
    cudaGetSymbolAddress((void**)&Bsum, g_Bs);
    cudaGetSymbolAddress((void**)&Wcb,  g_Wcb);
    __nv_bfloat16* Xs[2] = {X0, X1};

    const int SMEM_G = 3 * 128 * 72 * 2 * 2;     // 110592
    const int SMEM_H = (EPB * (2*LL + NCAPS*LL + NCAPS*4 + NCAPS + NCAPS*OUTC + OUTC + 8)) * 4;
    cudaFuncSetAttribute(gemm_lstm<272, 0>,
                         cudaFuncAttributeMaxDynamicSharedMemorySize, SMEM_G);
    cudaFuncSetAttribute(gemm_lstm<408, 1>,
                         cudaFuncAttributeMaxDynamicSharedMemorySize, SMEM_G);
    cudaFuncSetAttribute(head_kernel,
                         cudaFuncAttributeMaxDynamicSharedMemorySize, SMEM_H);

    const long long nSetup = (long long)BATCH * LL + (long long)NL * 2 * GATES * KCAT
                           + NL * GCOLS + NCAPS * OUTC * LL;
    setup_kernel<<<(int)((nSetup + 255) / 256), 256>>>(
        seq, sig, embed, w_ih, w_hh, b_ih, b_hh, W_caps, X0, Wcat, Bsum, Wcb);

    dim3 grid(5, BATCH / 128, 2);
    for (int l = 0; l < NL; ++l) {
        __nv_bfloat16* Xc = Xs[l & 1];
        __nv_bfloat16* Xn = Xs[(l + 1) & 1];
        const __nv_bfloat16* Wl = Wcat + (size_t)l * 2 * GATES * KCAT;
        const float* Bl = Bsum + (size_t)l * GCOLS;

        gemm_lstm<272, 0><<<grid, 256, SMEM_G>>>(Xc, Wl, Bl, Xn, Cf, Cb);
        gemm_lstm<408, 1><<<grid, 256, SMEM_G>>>(Xc, Wl, Bl, Xn, Cf, Cb);
    }

    head_kernel<<<BATCH / EPB, 128 * EPB, SMEM_H>>>(X1, conv_w, conv_b, Wcb,
                                                    fc1_w, fc1_b, fc2_w, fc2_b,
                                                    out, out_size);
}